// round 15
// baseline (speedup 1.0000x reference)
#include <cuda_runtime.h>
#include <cstdint>

// ---------------------------------------------------------------------------
// 3-layer transformer forward. B=4096, T=128, D=64, H=8, HD=8, DF=256, V=65.
// Round 15: single persistent mega-kernel. All deps are block-local (batch b
// always maps to block b%152), so the whole forward runs in one launch:
// per layer {stage attn weights; batch loop attn} {stage ffn weights; batch
// loop ffn (+lm_head/loss on last)}. Bodies = R14 verbatim.
// ---------------------------------------------------------------------------

#define NTOK (4096 * 128)
#define NBATCH 4096
#define TSEQ 128
#define DMODEL 64
#define NVOCAB 65
#define NHEAD 8
#define DFF 256
#define NLAYER 3
#define PGRID 152

__device__ float g_x[(size_t)NTOK * DMODEL];
__device__ float g_logits[(size_t)NTOK * NVOCAB];
__device__ float g_tokloss[NTOK];
__device__ double g_partial[512];

// ---------------------------------------------------------------------------
__device__ __forceinline__ unsigned f2tf(float f) {
    unsigned r;
    asm("cvt.rna.tf32.f32 %0, %1;" : "=r"(r) : "f"(f));
    return r;
}

__device__ __forceinline__ float ex2f(float f) {
    float r;
    asm("ex2.approx.f32 %0, %1;" : "=f"(r) : "f"(f));
    return r;
}

__device__ __forceinline__ float rcpf(float f) {
    float r;
    asm("rcp.approx.f32 %0, %1;" : "=f"(r) : "f"(f));
    return r;
}

__device__ __forceinline__ unsigned s2u(const void* p) {
    return (unsigned)__cvta_generic_to_shared(p);
}

__device__ __forceinline__ void ldsm4(unsigned* d, unsigned addr) {
    asm volatile(
        "ldmatrix.sync.aligned.m8n8.x4.shared.b16 {%0,%1,%2,%3}, [%4];"
        : "=r"(d[0]), "=r"(d[1]), "=r"(d[2]), "=r"(d[3]) : "r"(addr));
}

__device__ __forceinline__ void ldsm2(unsigned* d, unsigned addr) {
    asm volatile(
        "ldmatrix.sync.aligned.m8n8.x2.shared.b16 {%0,%1}, [%2];"
        : "=r"(d[0]), "=r"(d[1]) : "r"(addr));
}

__device__ __forceinline__ void mma_tf32(float* c, const unsigned* a,
                                         const unsigned* b) {
    asm volatile(
        "mma.sync.aligned.m16n8k8.row.col.f32.tf32.tf32.f32 "
        "{%0,%1,%2,%3},{%4,%5,%6,%7},{%8,%9},{%0,%1,%2,%3};"
        : "+f"(c[0]), "+f"(c[1]), "+f"(c[2]), "+f"(c[3])
        : "r"(a[0]), "r"(a[1]), "r"(a[2]), "r"(a[3]), "r"(b[0]), "r"(b[1]));
}

__device__ __forceinline__ void warp_ln_vals(float a0, float a1,
                                             float gg0, float gg1,
                                             float bb0, float bb1,
                                             float& o0, float& o1) {
    float s = a0 + a1;
#pragma unroll
    for (int o = 16; o; o >>= 1) s += __shfl_xor_sync(0xffffffffu, s, o);
    float mu = s * (1.0f / 64.0f);
    float d0 = a0 - mu, d1 = a1 - mu;
    float vs = d0 * d0 + d1 * d1;
#pragma unroll
    for (int o = 16; o; o >>= 1) vs += __shfl_xor_sync(0xffffffffu, vs, o);
    float inv = rsqrtf(vs * (1.0f / 64.0f) + 1e-5f);
    o0 = d0 * inv * gg0 + bb0;
    o1 = d1 * inv * gg1 + bb1;
}

__device__ __forceinline__ void attn_tile_proc(
    float* out, float& rs0, float& rs1,
    const unsigned* aS, const unsigned* bK, const unsigned* bV,
    int ni, int m, int r0, int lc, int src1, int src2, int par) {
    float c[4] = {0.f, 0.f, 0.f, 0.f};
    mma_tf32(c, aS, bK);
    if (8 * ni + 7 <= 16 * m) {
        c[0] = ex2f(c[0]); c[1] = ex2f(c[1]);
        c[2] = ex2f(c[2]); c[3] = ex2f(c[3]);
    } else {
        int j0 = 8 * ni + 2 * lc, j1 = j0 + 1;
        c[0] = (j0 <= r0) ? ex2f(c[0]) : 0.f;
        c[1] = (j1 <= r0) ? ex2f(c[1]) : 0.f;
        c[2] = (j0 <= r0 + 8) ? ex2f(c[2]) : 0.f;
        c[3] = (j1 <= r0 + 8) ? ex2f(c[3]) : 0.f;
    }
    rs0 += c[0] + c[1];
    rs1 += c[2] + c[3];
    float t0 = __shfl_sync(0xffffffffu, c[0], src1);
    float t1 = __shfl_sync(0xffffffffu, c[1], src1);
    float t2 = __shfl_sync(0xffffffffu, c[2], src1);
    float t3 = __shfl_sync(0xffffffffu, c[3], src1);
    float u0 = __shfl_sync(0xffffffffu, c[0], src2);
    float u1 = __shfl_sync(0xffffffffu, c[1], src2);
    float u2 = __shfl_sync(0xffffffffu, c[2], src2);
    float u3 = __shfl_sync(0xffffffffu, c[3], src2);
    unsigned aP[4];
    aP[0] = __float_as_uint(par ? t1 : t0);
    aP[1] = __float_as_uint(par ? t3 : t2);
    aP[2] = __float_as_uint(par ? u1 : u0);
    aP[3] = __float_as_uint(par ? u3 : u2);
    mma_tf32(out, aP, bV);
}

__device__ __forceinline__ void stage_relu32(
    unsigned* buf, const float acc[2][4][4], const float* __restrict__ b1,
    int gn0, int m0w, int lr, int lc) {
    const int ln0 = gn0 & 63;
#pragma unroll
    for (int mi = 0; mi < 2; mi++)
#pragma unroll
        for (int ni = 0; ni < 4; ni++) {
            int coll = ln0 + ni * 8 + 2 * lc;
            float2 bb = *(const float2*)(b1 + gn0 + ni * 8 + 2 * lc);
            int r = m0w + mi * 16 + lr;
            buf[r * 68 + coll]           = f2tf(fmaxf(acc[mi][ni][0] + bb.x, 0.f));
            buf[r * 68 + coll + 1]       = f2tf(fmaxf(acc[mi][ni][1] + bb.y, 0.f));
            buf[(r + 8) * 68 + coll]     = f2tf(fmaxf(acc[mi][ni][2] + bb.x, 0.f));
            buf[(r + 8) * 68 + coll + 1] = f2tf(fmaxf(acc[mi][ni][3] + bb.y, 0.f));
        }
}

// ---------------------------------------------------------------------------
// Mega-kernel: all 3 layers, attn+ffn phases, lm_head+loss at the end.
// smem = 56096 words (224384 B): attn overlay 51968 w, ffn overlay 56096 w.
// ---------------------------------------------------------------------------
__global__ __launch_bounds__(1024) void model_p(
    float* __restrict__ x,
    const int* __restrict__ idx, const float* __restrict__ te,
    const float* __restrict__ pe,
    const float* __restrict__ ln1g_, const float* __restrict__ ln1b_,
    const float* __restrict__ wq_, const float* __restrict__ wk_,
    const float* __restrict__ wv_, const float* __restrict__ wo_,
    const float* __restrict__ bo_,
    const float* __restrict__ ln2g_, const float* __restrict__ ln2b_,
    const float* __restrict__ w1_, const float* __restrict__ b1_,
    const float* __restrict__ w2_, const float* __restrict__ b2_,
    const float* __restrict__ lnfg, const float* __restrict__ lnfb,
    const float* __restrict__ lmw, const float* __restrict__ lmb,
    const int* __restrict__ tgt,
    float* __restrict__ logits, float* __restrict__ tokloss) {
    extern __shared__ unsigned sm[];

    const int tid = threadIdx.x;
    const int wid = tid >> 5, lane = tid & 31;
    const int lr = lane >> 2, lc = lane & 3;
    const int pl8 = ((lane >> 4) & 1) * 8;
    const int hk4 = ((lane >> 3) & 1) << 2;
    const int hi4 = (lane >> 4) << 2;

    for (int l = 0; l < NLAYER; l++) {
        const bool emb = (l == 0);
        const bool last = (l == NLAYER - 1);

        //==================== ATTENTION PHASE ================================
        {
            unsigned* As = sm;                   // [128][68]
            unsigned* qs = As + 8704;            // [128][68]
            unsigned* ks = qs + 8704;            // [128][68]
            unsigned* vsT = ks + 8704;           // [64][132]
            unsigned* Ws = vsT + 8448;           // [192][68]
            unsigned* Wos = Ws + 13056;          // [64][68]

            const float* lng = ln1g_ + l * 64;
            const float* lnb = ln1b_ + l * 64;
            const float* wq = wq_ + (long)l * 4096;
            const float* wk = wk_ + (long)l * 4096;
            const float* wv = wv_ + (long)l * 4096;
            const float* wo = wo_ + (long)l * 4096;
            const float* bo = bo_ + l * 64;

            __syncthreads();   // prior phase smem reads complete
            {
                const float* wsrc[3] = {wq, wk, wv};
#pragma unroll
                for (int s = 0; s < 3; s++) {
                    const float* W = wsrc[s];
#pragma unroll
                    for (int j = 0; j < 4; j++) {
                        int e = tid + j * 1024;
                        Ws[(s * 64 + (e & 63)) * 68 + (e >> 6)] = f2tf(W[e]);
                    }
                }
#pragma unroll
                for (int j = 0; j < 4; j++) {
                    int e = tid + j * 1024;          // e = k*64 + n
                    Wos[(e & 63) * 68 + (e >> 6)] = f2tf(wo[e]);
                }
            }
            const float gg0 = lng[lane], gg1 = lng[lane + 32];
            const float bbl0 = lnb[lane], bbl1 = lnb[lane + 32];

            const int wm = wid >> 2, wn = wid & 3;
            const int m0q = wm * 16, n0q = wn * 48;
            const unsigned qkv_a = s2u(As + (m0q + (lane & 15)) * 68 + hi4);
            const unsigned qkv_b4 = s2u(Ws + (n0q + pl8 + (lane & 7)) * 68 + hk4);
            const int h = wid & 7;
            const int mb = wid >> 3;
            const int m1 = mb, m2 = 7 - mb;
            const int nt1 = 2 * m1 + 2, nt2 = 2 * m2 + 2;
            const int r01 = 16 * m1 + lr, r02 = 16 * m2 + lr;
            const int src1 = (lane & 28) | (lc >> 1);
            const int src2 = src1 + 2;
            const int par = lc & 1;
            const unsigned aS1a = s2u(qs + (16 * m1 + (lane & 15)) * 68 + 8 * h + hi4);
            const unsigned aS2a = s2u(qs + (16 * m2 + (lane & 15)) * 68 + 8 * h + hi4);
            const unsigned kb4 = s2u(ks + (pl8 + (lane & 7)) * 68 + 8 * h + hk4);
            const unsigned vb4 = s2u(vsT + (8 * h + (lane & 7)) * 132 + hk4 + pl8);
            const int n0o = wn * 16;
            const unsigned wo_b4 = s2u(Wos + (n0o + pl8 + (lane & 7)) * 68 + hk4);

            for (int b = blockIdx.x; b < NBATCH; b += PGRID) {
                const long row0 = (long)b * 128;
                __syncthreads();

                // LN1 -> As (tf32); embed fused on layer 0
#pragma unroll
                for (int rr = 0; rr < 4; rr++) {
                    int r = wid + rr * 32;
                    float a0, a1;
                    if (emb) {
                        int id = idx[row0 + r];
                        a0 = te[id * 64 + lane] + pe[r * 64 + lane];
                        a1 = te[id * 64 + lane + 32] + pe[r * 64 + lane + 32];
                        x[(row0 + r) * 64 + lane] = a0;
                        x[(row0 + r) * 64 + lane + 32] = a1;
                    } else {
                        a0 = x[(row0 + r) * 64 + lane];
                        a1 = x[(row0 + r) * 64 + lane + 32];
                    }
                    float o0, o1;
                    warp_ln_vals(a0, a1, gg0, gg1, bbl0, bbl1, o0, o1);
                    As[r * 68 + lane] = f2tf(o0);
                    As[r * 68 + lane + 32] = f2tf(o1);
                }
                __syncthreads();

                // QKV MMA (16x48, paired B) -> qs, ks, vsT
                {
                    float acc[6][4];
#pragma unroll
                    for (int ni = 0; ni < 6; ni++)
#pragma unroll
                        for (int e = 0; e < 4; e++) acc[ni][e] = 0.0f;
#pragma unroll
                    for (int k0 = 0; k0 < 64; k0 += 8) {
                        unsigned a[4];
                        ldsm4(a, qkv_a + k0 * 4);
#pragma unroll
                        for (int p = 0; p < 3; p++) {
                            unsigned bp[4];
                            ldsm4(bp, qkv_b4 + (p * 16 * 68 + k0) * 4);
                            mma_tf32(acc[2 * p], a, bp);
                            mma_tf32(acc[2 * p + 1], a, bp + 2);
                        }
                    }
#pragma unroll
                    for (int ni = 0; ni < 6; ni++) {
                        int cg = n0q + ni * 8;
                        if (cg < 64) {   // q, pre-scaled by log2e/sqrt(8)
                            const float sc = 0.35355339059327373f * 1.4426950408889634f;
                            int col = cg + 2 * lc;
                            *(uint2*)(qs + (m0q + lr) * 68 + col) =
                                make_uint2(f2tf(acc[ni][0] * sc), f2tf(acc[ni][1] * sc));
                            *(uint2*)(qs + (m0q + lr + 8) * 68 + col) =
                                make_uint2(f2tf(acc[ni][2] * sc), f2tf(acc[ni][3] * sc));
                        } else if (cg < 128) {           // k
                            int col = cg - 64 + 2 * lc;
                            *(uint2*)(ks + (m0q + lr) * 68 + col) =
                                make_uint2(f2tf(acc[ni][0]), f2tf(acc[ni][1]));
                            *(uint2*)(ks + (m0q + lr + 8) * 68 + col) =
                                make_uint2(f2tf(acc[ni][2]), f2tf(acc[ni][3]));
                        } else {                         // v, transposed
                            int hd = cg - 128 + 2 * lc;
                            vsT[hd * 132 + m0q + lr]           = f2tf(acc[ni][0]);
                            vsT[(hd + 1) * 132 + m0q + lr]     = f2tf(acc[ni][1]);
                            vsT[hd * 132 + m0q + lr + 8]       = f2tf(acc[ni][2]);
                            vsT[(hd + 1) * 132 + m0q + lr + 8] = f2tf(acc[ni][3]);
                        }
                    }
                }
                __syncthreads();

                // fused-pair MMA attention -> As
                {
                    unsigned aS1[4], aS2[4];
                    ldsm4(aS1, aS1a);
                    ldsm4(aS2, aS2a);
                    float out1[4] = {0.f, 0.f, 0.f, 0.f};
                    float out2[4] = {0.f, 0.f, 0.f, 0.f};
                    float rs10 = 0.f, rs11 = 0.f, rs20 = 0.f, rs21 = 0.f;
                    unsigned kaddr = kb4, vaddr = vb4;
                    for (int ni = 0; ni < nt2; ni += 2) {
                        unsigned bK[4], bV[4];
                        ldsm4(bK, kaddr);
                        ldsm4(bV, vaddr);
                        kaddr += 2 * 8 * 68 * 4;
                        vaddr += 64;
                        attn_tile_proc(out2, rs20, rs21, aS2, bK, bV, ni, m2,
                                       r02, lc, src1, src2, par);
                        attn_tile_proc(out2, rs20, rs21, aS2, bK + 2, bV + 2,
                                       ni + 1, m2, r02, lc, src1, src2, par);
                        if (ni < nt1) {
                            attn_tile_proc(out1, rs10, rs11, aS1, bK, bV, ni,
                                           m1, r01, lc, src1, src2, par);
                            attn_tile_proc(out1, rs10, rs11, aS1, bK + 2,
                                           bV + 2, ni + 1, m1, r01, lc, src1,
                                           src2, par);
                        }
                    }
#pragma unroll
                    for (int t = 0; t < 2; t++) {
                        float a0 = t ? rs20 : rs10, a1 = t ? rs21 : rs11;
                        const float* ov = t ? out2 : out1;
                        int r0 = t ? r02 : r01;
                        a0 += __shfl_xor_sync(0xffffffffu, a0, 1);
                        a0 += __shfl_xor_sync(0xffffffffu, a0, 2);
                        a1 += __shfl_xor_sync(0xffffffffu, a1, 1);
                        a1 += __shfl_xor_sync(0xffffffffu, a1, 2);
                        float inv0 = rcpf(a0), inv1 = rcpf(a1);
                        unsigned* d0 = As + r0 * 68 + 8 * h + 2 * lc;
                        unsigned* d1 = As + (r0 + 8) * 68 + 8 * h + 2 * lc;
                        d0[0] = f2tf(ov[0] * inv0); d0[1] = f2tf(ov[1] * inv0);
                        d1[0] = f2tf(ov[2] * inv1); d1[1] = f2tf(ov[3] * inv1);
                    }
                }
                __syncthreads();

                // Wo MMA (16x16, paired B) + bias + residual rmw on x
                {
                    float acc[2][4];
#pragma unroll
                    for (int ni = 0; ni < 2; ni++)
#pragma unroll
                        for (int e = 0; e < 4; e++) acc[ni][e] = 0.0f;
#pragma unroll
                    for (int k0 = 0; k0 < 64; k0 += 8) {
                        unsigned a[4];
                        ldsm4(a, qkv_a + k0 * 4);
                        unsigned bp[4];
                        ldsm4(bp, wo_b4 + k0 * 4);
                        mma_tf32(acc[0], a, bp);
                        mma_tf32(acc[1], a, bp + 2);
                    }
#pragma unroll
                    for (int ni = 0; ni < 2; ni++) {
                        int col = n0o + ni * 8 + 2 * lc;
                        float2 bb = *(const float2*)(bo + col);
                        float2* p0 = (float2*)(x + (row0 + m0q + lr) * 64 + col);
                        float2* p1 = (float2*)(x + (row0 + m0q + lr + 8) * 64 + col);
                        float2 r0v = *p0, r1v = *p1;
                        r0v.x += acc[ni][0] + bb.x;
                        r0v.y += acc[ni][1] + bb.y;
                        r1v.x += acc[ni][2] + bb.x;
                        r1v.y += acc[ni][3] + bb.y;
                        *p0 = r0v;
                        *p1 = r1v;
                    }
                }
            }
        }

        //==================== FFN PHASE ======================================
        {
            unsigned* As = sm;                   // [128][68]
            unsigned* W1s = As + 8704;           // [256][68]
            unsigned* W2s = W1s + 17408;         // [64][260]
            unsigned* ext = W2s + 16640;
            unsigned* As2 = last ? ext + 4896 : ext;
            unsigned* lmws = ext;                // [72][68]   (last)
            float* ls = (float*)(ext + 4896);    // [128][66]  (last)

            const float* lng = ln2g_ + l * 64;
            const float* lnb = ln2b_ + l * 64;
            const float* w1 = w1_ + (long)l * 64 * 256;
            const float* b1 = b1_ + l * 256;
            const float* w2 = w2_ + (long)l * 256 * 64;
            const float* b2 = b2_ + l * 64;

            __syncthreads();   // attn phase smem reads complete
#pragma unroll
            for (int j = 0; j < 16; j++) {
                int e = tid + j * 1024;
                W1s[(e & 255) * 68 + (e >> 8)] = f2tf(w1[e]);
            }
#pragma unroll
            for (int j = 0; j < 16; j++) {
                int e = tid + j * 1024;
                W2s[(e & 63) * 260 + (e >> 6)] = f2tf(w2[e]);
            }
            if (last) {
                if (tid < 7 * 68) lmws[65 * 68 + tid] = 0u;
#pragma unroll
                for (int j = 0; j < 5; j++) {
                    int e = tid + j * 1024;
                    if (e < 65 * 64) {
                        int n = e >> 6, k = e & 63;
                        lmws[n * 68 + k] = f2tf(lmw[k * 65 + n]);
                    }
                }
            }
            const float gg0 = lng[lane], gg1 = lng[lane + 32];
            const float bbl0 = lnb[lane], bbl1 = lnb[lane + 32];

            const int wm2 = wid >> 3, wn8 = wid & 7;
            const int m0w = wm2 * 32, gn0 = wn8 * 32;
            const unsigned g1a0 = s2u(As + (m0w + (lane & 15)) * 68 + hi4);
            const unsigned g1a1 = s2u(As + (m0w + 16 + (lane & 15)) * 68 + hi4);
            const unsigned g1b = s2u(W1s + (gn0 + pl8 + (lane & 7)) * 68 + hk4);
            const int chunk_own = wn8 >> 1;

            const int wm = wid >> 2, wn = wid & 3;
            const int m0 = wm * 16;
            const int n02 = wn * 16;
            const unsigned abase0 = s2u(As + (m0 + (lane & 15)) * 68 + hi4);
            const unsigned abase1 = s2u(As2 + (m0 + (lane & 15)) * 68 + hi4);
            const unsigned b2base4 = s2u(W2s + (n02 + pl8 + (lane & 7)) * 260 + hk4);

            for (int b = blockIdx.x; b < NBATCH; b += PGRID) {
                const long row0 = (long)b * 128;
                __syncthreads();

                // LN2 -> As (tf32)
#pragma unroll
                for (int rr = 0; rr < 4; rr++) {
                    int r = wid + rr * 32;
                    float a0 = x[(row0 + r) * 64 + lane];
                    float a1 = x[(row0 + r) * 64 + lane + 32];
                    float o0, o1;
                    warp_ln_vals(a0, a1, gg0, gg1, bbl0, bbl1, o0, o1);
                    As[r * 68 + lane] = f2tf(o0);
                    As[r * 68 + lane + 32] = f2tf(o1);
                }
                __syncthreads();

                // GEMM1 (32 warps x 32x32)
                float acc[2][4][4];
#pragma unroll
                for (int mi = 0; mi < 2; mi++)
#pragma unroll
                    for (int ni = 0; ni < 4; ni++)
#pragma unroll
                        for (int e = 0; e < 4; e++) acc[mi][ni][e] = 0.0f;
#pragma unroll
                for (int k0 = 0; k0 < 64; k0 += 8) {
                    unsigned a0[4], a1[4];
                    ldsm4(a0, g1a0 + k0 * 4);
                    ldsm4(a1, g1a1 + k0 * 4);
#pragma unroll
                    for (int p = 0; p < 2; p++) {
                        unsigned bp[4];
                        ldsm4(bp, g1b + (p * 16 * 68 + k0) * 4);
                        mma_tf32(acc[0][2 * p], a0, bp);
                        mma_tf32(acc[0][2 * p + 1], a0, bp + 2);
                        mma_tf32(acc[1][2 * p], a1, bp);
                        mma_tf32(acc[1][2 * p + 1], a1, bp + 2);
                    }
                }

                // GEMM2 (32 warps x 16x16), relu(h1) staged
                float acc2[2][4];
#pragma unroll
                for (int ni = 0; ni < 2; ni++)
#pragma unroll
                    for (int e = 0; e < 4; e++) acc2[ni][e] = 0.0f;

                if (!last) {
                    __syncthreads();
                    if (chunk_own == 0) stage_relu32(As, acc, b1, gn0, m0w, lr, lc);
                    __syncthreads();
#pragma unroll
                    for (int kc = 0; kc < 4; kc++) {
                        if (kc < 3 && chunk_own == kc + 1)
                            stage_relu32((kc & 1) ? As : As2, acc, b1, gn0, m0w, lr, lc);
                        unsigned ab = (kc & 1) ? abase1 : abase0;
#pragma unroll
                        for (int k0 = 0; k0 < 64; k0 += 8) {
                            unsigned a[4];
                            ldsm4(a, ab + k0 * 4);
                            unsigned bp[4];
                            ldsm4(bp, b2base4 + (kc * 64 + k0) * 4);
                            mma_tf32(acc2[0], a, bp);
                            mma_tf32(acc2[1], a, bp + 2);
                        }
                        if (kc < 3) __syncthreads();
                    }
                } else {
#pragma unroll
                    for (int kc = 0; kc < 4; kc++) {
                        __syncthreads();
                        if (chunk_own == kc) stage_relu32(As, acc, b1, gn0, m0w, lr, lc);
                        __syncthreads();
#pragma unroll
                        for (int k0 = 0; k0 < 64; k0 += 8) {
                            unsigned a[4];
                            ldsm4(a, abase0 + k0 * 4);
                            unsigned bp[4];
                            ldsm4(bp, b2base4 + (kc * 64 + k0) * 4);
                            mma_tf32(acc2[0], a, bp);
                            mma_tf32(acc2[1], a, bp + 2);
                        }
                    }
                }

                // epilogue: + bias + residual rmw on x
#pragma unroll
                for (int ni = 0; ni < 2; ni++) {
                    int col = n02 + ni * 8 + 2 * lc;
                    float2 bb = *(const float2*)(b2 + col);
                    float2* p0 = (float2*)(x + (row0 + m0 + lr) * 64 + col);
                    float2* p1 = (float2*)(x + (row0 + m0 + lr + 8) * 64 + col);
                    float2 r0v = *p0, r1v = *p1;
                    r0v.x += acc2[ni][0] + bb.x;
                    r0v.y += acc2[ni][1] + bb.y;
                    r1v.x += acc2[ni][2] + bb.x;
                    r1v.y += acc2[ni][3] + bb.y;
                    *p0 = r0v;
                    *p1 = r1v;
                }

                // last layer: LNf + lm_head + logits + loss
                if (last) {
                    __syncthreads();
                    {
                        float fg0 = lnfg[lane], fg1 = lnfg[lane + 32];
                        float fb0 = lnfb[lane], fb1 = lnfb[lane + 32];
#pragma unroll
                        for (int rr = 0; rr < 4; rr++) {
                            int r = wid + rr * 32;
                            float a0 = x[(row0 + r) * 64 + lane];
                            float a1 = x[(row0 + r) * 64 + lane + 32];
                            float o0, o1;
                            warp_ln_vals(a0, a1, fg0, fg1, fb0, fb1, o0, o1);
                            As[r * 68 + lane] = f2tf(o0);
                            As[r * 68 + lane + 32] = f2tf(o1);
                        }
                    }
                    __syncthreads();

                    const int mh = (wid >> 2) * 16;
                    const int nq = wid & 3;
                    const int nt0 = (nq == 0) ? 0 : (nq == 1) ? 3 : (nq == 2) ? 5 : 7;
                    const int ntn = (nq == 0) ? 3 : 2;
                    float lacc[3][4];
#pragma unroll
                    for (int ni = 0; ni < 3; ni++)
#pragma unroll
                        for (int e = 0; e < 4; e++) lacc[ni][e] = 0.0f;
                    unsigned la = s2u(As + (mh + (lane & 15)) * 68 + hi4);
                    unsigned lb = s2u(lmws + (nt0 * 8 + (lane & 7)) * 68 +
                                      (((lane >> 3) & 1) << 2));
#pragma unroll
                    for (int k0 = 0; k0 < 64; k0 += 8) {
                        unsigned a[4];
                        ldsm4(a, la + k0 * 4);
#pragma unroll
                        for (int ni = 0; ni < 3; ni++) {
                            if (ni < ntn) {
                                unsigned bfr[2];
                                ldsm2(bfr, lb + (ni * 8 * 68 + k0) * 4);
                                mma_tf32(lacc[ni], a, bfr);
                            }
                        }
                    }
#pragma unroll
                    for (int ni = 0; ni < 3; ni++) {
                        if (ni < ntn) {
                            int col = (nt0 + ni) * 8 + 2 * lc;
                            if (col < 65) {
                                float bb = lmb[col];
                                ls[(mh + lr) * 66 + col] = lacc[ni][0] + bb;
                                ls[(mh + lr + 8) * 66 + col] = lacc[ni][2] + bb;
                            }
                            if (col + 1 < 65) {
                                float bb = lmb[col + 1];
                                ls[(mh + lr) * 66 + col + 1] = lacc[ni][1] + bb;
                                ls[(mh + lr + 8) * 66 + col + 1] = lacc[ni][3] + bb;
                            }
                        }
                    }
                    __syncthreads();

                    for (int i = tid; i < 128 * 65; i += 1024) {
                        int r = i / 65, c = i - r * 65;
                        logits[row0 * 65 + i] = ls[r * 66 + c];
                    }
#pragma unroll
                    for (int rr = 0; rr < 4; rr++) {
                        int t = wid * 4 + rr;
                        float v0 = ls[t * 66 + lane];
                        float v1 = ls[t * 66 + lane + 32];
                        float v2 = (lane == 0) ? ls[t * 66 + 64] : -1e30f;
                        float mx = fmaxf(fmaxf(v0, v1), v2);
#pragma unroll
                        for (int o = 16; o; o >>= 1)
                            mx = fmaxf(mx, __shfl_xor_sync(0xffffffffu, mx, o));
                        float se = __expf(v0 - mx) + __expf(v1 - mx) + __expf(v2 - mx);
#pragma unroll
                        for (int o = 16; o; o >>= 1)
                            se += __shfl_xor_sync(0xffffffffu, se, o);
                        if (lane == 0) {
                            int tg = tgt[row0 + t];
                            tokloss[row0 + t] = -(ls[t * 66 + tg] - mx - __logf(se));
                        }
                    }
                }
            }
        }
    }
}

// ---------------------------------------------------------------------------
__global__ void reduce1_kernel(const float* __restrict__ tl,
                               double* __restrict__ part) {
    __shared__ double smd[256];
    long base = (long)blockIdx.x * (NTOK / 512);
    double s = 0.0;
    for (int i = threadIdx.x; i < NTOK / 512; i += 256) s += (double)tl[base + i];
    smd[threadIdx.x] = s;
    __syncthreads();
    for (int o = 128; o; o >>= 1) {
        if (threadIdx.x < o) smd[threadIdx.x] += smd[threadIdx.x + o];
        __syncthreads();
    }
    if (threadIdx.x == 0) part[blockIdx.x] = smd[0];
}

__global__ void reduce2_kernel(const double* __restrict__ part,
                               float* __restrict__ out) {
    __shared__ double smd[512];
    smd[threadIdx.x] = part[threadIdx.x];
    __syncthreads();
    for (int o = 256; o; o >>= 1) {
        if (threadIdx.x < o) smd[threadIdx.x] += smd[threadIdx.x + o];
        __syncthreads();
    }
    if (threadIdx.x == 0) out[0] = (float)(smd[0] / (double)NTOK);
}

// ---------------------------------------------------------------------------
extern "C" void kernel_launch(void* const* d_in, const int* in_sizes, int n_in,
                              void* d_out, int out_size) {
    const float* tok_emb = (const float*)d_in[0];
    const float* pos_emb = (const float*)d_in[1];
    const float* ln1_g   = (const float*)d_in[2];
    const float* ln1_b   = (const float*)d_in[3];
    const float* wq      = (const float*)d_in[4];
    const float* wk      = (const float*)d_in[5];
    const float* wv      = (const float*)d_in[6];
    const float* wo      = (const float*)d_in[7];
    const float* bo      = (const float*)d_in[8];
    const float* ln2_g   = (const float*)d_in[9];
    const float* ln2_b   = (const float*)d_in[10];
    const float* w1      = (const float*)d_in[11];
    const float* b1      = (const float*)d_in[12];
    const float* w2      = (const float*)d_in[13];
    const float* b2      = (const float*)d_in[14];
    const float* lnf_g   = (const float*)d_in[15];
    const float* lnf_b   = (const float*)d_in[16];
    const float* lm_w    = (const float*)d_in[17];
    const float* lm_b    = (const float*)d_in[18];
    const int*   idx     = (const int*)d_in[19];
    const int*   targets = (const int*)d_in[20];

    float *x, *lg, *tl;
    double* part;
    cudaGetSymbolAddress((void**)&x,  g_x);
    cudaGetSymbolAddress((void**)&lg, g_logits);
    cudaGetSymbolAddress((void**)&tl, g_tokloss);
    cudaGetSymbolAddress((void**)&part, g_partial);

    float* outp = (float*)d_out;
    const long LSZ = (long)NTOK * NVOCAB;
    float* logits = ((long)out_size >= LSZ) ? outp : lg;
    float* lossp;
    if ((long)out_size >= LSZ + 1)      lossp = outp + LSZ;
    else if (out_size == 1)             lossp = outp;
    else                                lossp = tl;

    const int SMEM = 56096 * 4;   // 224384 B
    cudaFuncSetAttribute(model_p, cudaFuncAttributeMaxDynamicSharedMemorySize, SMEM);

    model_p<<<PGRID, 1024, SMEM>>>(
        x, idx, tok_emb, pos_emb,
        ln1_g, ln1_b, wq, wk, wv, wo, bo,
        ln2_g, ln2_b, w1, b1, w2, b2,
        lnf_g, lnf_b, lm_w, lm_b, targets, logits, tl);
    reduce1_kernel<<<512, 256>>>(tl, part);
    reduce2_kernel<<<1, 512>>>(part, lossp);
}

// round 16
// speedup vs baseline: 1.2464x; 1.2464x over previous
#include <cuda_runtime.h>
#include <cuda_fp16.h>
#include <cstdint>

// ---------------------------------------------------------------------------
// 3-layer transformer forward. B=4096, T=128, D=64, H=8, HD=8, DF=256, V=65.
// Round 16: R14 structure (best); FFN + lm_head GEMMs converted to fp16
// operands (m16n8k16) — halves smem bytes/MAC and MMA instruction count.
// fp16 significand == tf32 significand (11 bits) -> same rounding error.
// Attention kernel stays tf32 (head_dim=8 < k16).
// ---------------------------------------------------------------------------

#define NTOK (4096 * 128)
#define NBATCH 4096
#define TSEQ 128
#define DMODEL 64
#define NVOCAB 65
#define NHEAD 8
#define DFF 256
#define NLAYER 3
#define PGRID 152

__device__ float g_x[(size_t)NTOK * DMODEL];
__device__ float g_logits[(size_t)NTOK * NVOCAB];
__device__ float g_tokloss[NTOK];
__device__ double g_partial[512];

// ---------------------------------------------------------------------------
__device__ __forceinline__ unsigned f2tf(float f) {
    unsigned r;
    asm("cvt.rna.tf32.f32 %0, %1;" : "=r"(r) : "f"(f));
    return r;
}

__device__ __forceinline__ float ex2f(float f) {
    float r;
    asm("ex2.approx.f32 %0, %1;" : "=f"(r) : "f"(f));
    return r;
}

__device__ __forceinline__ float rcpf(float f) {
    float r;
    asm("rcp.approx.f32 %0, %1;" : "=f"(r) : "f"(f));
    return r;
}

__device__ __forceinline__ unsigned s2u(const void* p) {
    return (unsigned)__cvta_generic_to_shared(p);
}

__device__ __forceinline__ void ldsm4(unsigned* d, unsigned addr) {
    asm volatile(
        "ldmatrix.sync.aligned.m8n8.x4.shared.b16 {%0,%1,%2,%3}, [%4];"
        : "=r"(d[0]), "=r"(d[1]), "=r"(d[2]), "=r"(d[3]) : "r"(addr));
}

__device__ __forceinline__ void ldsm2(unsigned* d, unsigned addr) {
    asm volatile(
        "ldmatrix.sync.aligned.m8n8.x2.shared.b16 {%0,%1}, [%2];"
        : "=r"(d[0]), "=r"(d[1]) : "r"(addr));
}

__device__ __forceinline__ void mma_tf32(float* c, const unsigned* a,
                                         const unsigned* b) {
    asm volatile(
        "mma.sync.aligned.m16n8k8.row.col.f32.tf32.tf32.f32 "
        "{%0,%1,%2,%3},{%4,%5,%6,%7},{%8,%9},{%0,%1,%2,%3};"
        : "+f"(c[0]), "+f"(c[1]), "+f"(c[2]), "+f"(c[3])
        : "r"(a[0]), "r"(a[1]), "r"(a[2]), "r"(a[3]), "r"(b[0]), "r"(b[1]));
}

__device__ __forceinline__ void mma_f16(float* c, const unsigned* a,
                                        const unsigned* b) {
    asm volatile(
        "mma.sync.aligned.m16n8k16.row.col.f32.f16.f16.f32 "
        "{%0,%1,%2,%3},{%4,%5,%6,%7},{%8,%9},{%0,%1,%2,%3};"
        : "+f"(c[0]), "+f"(c[1]), "+f"(c[2]), "+f"(c[3])
        : "r"(a[0]), "r"(a[1]), "r"(a[2]), "r"(a[3]), "r"(b[0]), "r"(b[1]));
}

__device__ __forceinline__ void warp_ln_vals(float a0, float a1,
                                             float gg0, float gg1,
                                             float bb0, float bb1,
                                             float& o0, float& o1) {
    float s = a0 + a1;
#pragma unroll
    for (int o = 16; o; o >>= 1) s += __shfl_xor_sync(0xffffffffu, s, o);
    float mu = s * (1.0f / 64.0f);
    float d0 = a0 - mu, d1 = a1 - mu;
    float vs = d0 * d0 + d1 * d1;
#pragma unroll
    for (int o = 16; o; o >>= 1) vs += __shfl_xor_sync(0xffffffffu, vs, o);
    float inv = rsqrtf(vs * (1.0f / 64.0f) + 1e-5f);
    o0 = d0 * inv * gg0 + bb0;
    o1 = d1 * inv * gg1 + bb1;
}

__device__ __forceinline__ void attn_tile_proc(
    float* out, float& rs0, float& rs1,
    const unsigned* aS, const unsigned* bK, const unsigned* bV,
    int ni, int m, int r0, int lc, int src1, int src2, int par) {
    float c[4] = {0.f, 0.f, 0.f, 0.f};
    mma_tf32(c, aS, bK);
    if (8 * ni + 7 <= 16 * m) {
        c[0] = ex2f(c[0]); c[1] = ex2f(c[1]);
        c[2] = ex2f(c[2]); c[3] = ex2f(c[3]);
    } else {
        int j0 = 8 * ni + 2 * lc, j1 = j0 + 1;
        c[0] = (j0 <= r0) ? ex2f(c[0]) : 0.f;
        c[1] = (j1 <= r0) ? ex2f(c[1]) : 0.f;
        c[2] = (j0 <= r0 + 8) ? ex2f(c[2]) : 0.f;
        c[3] = (j1 <= r0 + 8) ? ex2f(c[3]) : 0.f;
    }
    rs0 += c[0] + c[1];
    rs1 += c[2] + c[3];
    float t0 = __shfl_sync(0xffffffffu, c[0], src1);
    float t1 = __shfl_sync(0xffffffffu, c[1], src1);
    float t2 = __shfl_sync(0xffffffffu, c[2], src1);
    float t3 = __shfl_sync(0xffffffffu, c[3], src1);
    float u0 = __shfl_sync(0xffffffffu, c[0], src2);
    float u1 = __shfl_sync(0xffffffffu, c[1], src2);
    float u2 = __shfl_sync(0xffffffffu, c[2], src2);
    float u3 = __shfl_sync(0xffffffffu, c[3], src2);
    unsigned aP[4];
    aP[0] = __float_as_uint(par ? t1 : t0);
    aP[1] = __float_as_uint(par ? t3 : t2);
    aP[2] = __float_as_uint(par ? u1 : u0);
    aP[3] = __float_as_uint(par ? u3 : u2);
    mma_tf32(out, aP, bV);
}

// ---------------------------------------------------------------------------
// Persistent attention kernel (R14 verbatim, tf32). EMB=1: embed fused.
// smem (words): As[128][68] | qs[128][68] | ks[128][68] | vsT[64][132] |
//               Ws[192][68] | Wos[64][68]  = 51968 words = 207872 B.
// ---------------------------------------------------------------------------
template <int EMB>
__global__ __launch_bounds__(1024) void attn_p(
    float* __restrict__ x,
    const int* __restrict__ idx, const float* __restrict__ te,
    const float* __restrict__ pe,
    const float* __restrict__ lng, const float* __restrict__ lnb,
    const float* __restrict__ wq, const float* __restrict__ wk,
    const float* __restrict__ wv, const float* __restrict__ wo,
    const float* __restrict__ bo) {
    extern __shared__ unsigned sm[];
    unsigned* As = sm;                   // [128][68]
    unsigned* qs = As + 8704;            // [128][68]
    unsigned* ks = qs + 8704;            // [128][68]
    unsigned* vsT = ks + 8704;           // [64][132]
    unsigned* Ws = vsT + 8448;           // [192][68]
    unsigned* Wos = Ws + 13056;          // [64][68]

    const int tid = threadIdx.x;
    const int wid = tid >> 5, lane = tid & 31;
    const int lr = lane >> 2, lc = lane & 3;
    const int pl8 = ((lane >> 4) & 1) * 8;
    const int hk4 = ((lane >> 3) & 1) << 2;
    const int hi4 = (lane >> 4) << 2;

    {
        const float* wsrc[3] = {wq, wk, wv};
#pragma unroll
        for (int s = 0; s < 3; s++) {
            const float* W = wsrc[s];
#pragma unroll
            for (int j = 0; j < 4; j++) {
                int e = tid + j * 1024;
                Ws[(s * 64 + (e & 63)) * 68 + (e >> 6)] = f2tf(W[e]);
            }
        }
#pragma unroll
        for (int j = 0; j < 4; j++) {
            int e = tid + j * 1024;          // e = k*64 + n
            Wos[(e & 63) * 68 + (e >> 6)] = f2tf(wo[e]);
        }
    }
    const float gg0 = lng[lane], gg1 = lng[lane + 32];
    const float bbl0 = lnb[lane], bbl1 = lnb[lane + 32];

    const int wm = wid >> 2, wn = wid & 3;
    const int m0q = wm * 16, n0q = wn * 48;
    const unsigned qkv_a = s2u(As + (m0q + (lane & 15)) * 68 + hi4);
    const unsigned qkv_b4 = s2u(Ws + (n0q + pl8 + (lane & 7)) * 68 + hk4);
    const int h = wid & 7;
    const int mb = wid >> 3;
    const int m1 = mb, m2 = 7 - mb;
    const int nt1 = 2 * m1 + 2, nt2 = 2 * m2 + 2;
    const int r01 = 16 * m1 + lr, r02 = 16 * m2 + lr;
    const int src1 = (lane & 28) | (lc >> 1);
    const int src2 = src1 + 2;
    const int par = lc & 1;
    const unsigned aS1a = s2u(qs + (16 * m1 + (lane & 15)) * 68 + 8 * h + hi4);
    const unsigned aS2a = s2u(qs + (16 * m2 + (lane & 15)) * 68 + 8 * h + hi4);
    const unsigned kb4 = s2u(ks + (pl8 + (lane & 7)) * 68 + 8 * h + hk4);
    const unsigned vb4 = s2u(vsT + (8 * h + (lane & 7)) * 132 + hk4 + pl8);
    const int n0o = wn * 16;
    const unsigned wo_b4 = s2u(Wos + (n0o + pl8 + (lane & 7)) * 68 + hk4);

    for (int b = blockIdx.x; b < NBATCH; b += PGRID) {
        const long row0 = (long)b * 128;
        __syncthreads();

#pragma unroll
        for (int rr = 0; rr < 4; rr++) {
            int r = wid + rr * 32;
            float a0, a1;
            if (EMB) {
                int id = idx[row0 + r];
                a0 = te[id * 64 + lane] + pe[r * 64 + lane];
                a1 = te[id * 64 + lane + 32] + pe[r * 64 + lane + 32];
                x[(row0 + r) * 64 + lane] = a0;
                x[(row0 + r) * 64 + lane + 32] = a1;
            } else {
                a0 = x[(row0 + r) * 64 + lane];
                a1 = x[(row0 + r) * 64 + lane + 32];
            }
            float o0, o1;
            warp_ln_vals(a0, a1, gg0, gg1, bbl0, bbl1, o0, o1);
            As[r * 68 + lane] = f2tf(o0);
            As[r * 68 + lane + 32] = f2tf(o1);
        }
        __syncthreads();

        {
            float acc[6][4];
#pragma unroll
            for (int ni = 0; ni < 6; ni++)
#pragma unroll
                for (int e = 0; e < 4; e++) acc[ni][e] = 0.0f;
#pragma unroll
            for (int k0 = 0; k0 < 64; k0 += 8) {
                unsigned a[4];
                ldsm4(a, qkv_a + k0 * 4);
#pragma unroll
                for (int p = 0; p < 3; p++) {
                    unsigned bp[4];
                    ldsm4(bp, qkv_b4 + (p * 16 * 68 + k0) * 4);
                    mma_tf32(acc[2 * p], a, bp);
                    mma_tf32(acc[2 * p + 1], a, bp + 2);
                }
            }
#pragma unroll
            for (int ni = 0; ni < 6; ni++) {
                int cg = n0q + ni * 8;
                if (cg < 64) {     // q, pre-scaled by log2e/sqrt(8) for ex2
                    const float sc = 0.35355339059327373f * 1.4426950408889634f;
                    int col = cg + 2 * lc;
                    *(uint2*)(qs + (m0q + lr) * 68 + col) =
                        make_uint2(f2tf(acc[ni][0] * sc), f2tf(acc[ni][1] * sc));
                    *(uint2*)(qs + (m0q + lr + 8) * 68 + col) =
                        make_uint2(f2tf(acc[ni][2] * sc), f2tf(acc[ni][3] * sc));
                } else if (cg < 128) {               // k
                    int col = cg - 64 + 2 * lc;
                    *(uint2*)(ks + (m0q + lr) * 68 + col) =
                        make_uint2(f2tf(acc[ni][0]), f2tf(acc[ni][1]));
                    *(uint2*)(ks + (m0q + lr + 8) * 68 + col) =
                        make_uint2(f2tf(acc[ni][2]), f2tf(acc[ni][3]));
                } else {                             // v, transposed
                    int hd = cg - 128 + 2 * lc;
                    vsT[hd * 132 + m0q + lr]           = f2tf(acc[ni][0]);
                    vsT[(hd + 1) * 132 + m0q + lr]     = f2tf(acc[ni][1]);
                    vsT[hd * 132 + m0q + lr + 8]       = f2tf(acc[ni][2]);
                    vsT[(hd + 1) * 132 + m0q + lr + 8] = f2tf(acc[ni][3]);
                }
            }
        }
        __syncthreads();

        {
            unsigned aS1[4], aS2[4];
            ldsm4(aS1, aS1a);
            ldsm4(aS2, aS2a);
            float out1[4] = {0.f, 0.f, 0.f, 0.f}, out2[4] = {0.f, 0.f, 0.f, 0.f};
            float rs10 = 0.f, rs11 = 0.f, rs20 = 0.f, rs21 = 0.f;
            unsigned kaddr = kb4, vaddr = vb4;
            for (int ni = 0; ni < nt2; ni += 2) {
                unsigned bK[4], bV[4];
                ldsm4(bK, kaddr);
                ldsm4(bV, vaddr);
                kaddr += 2 * 8 * 68 * 4;
                vaddr += 64;
                attn_tile_proc(out2, rs20, rs21, aS2, bK, bV, ni, m2, r02,
                               lc, src1, src2, par);
                attn_tile_proc(out2, rs20, rs21, aS2, bK + 2, bV + 2, ni + 1,
                               m2, r02, lc, src1, src2, par);
                if (ni < nt1) {
                    attn_tile_proc(out1, rs10, rs11, aS1, bK, bV, ni, m1, r01,
                                   lc, src1, src2, par);
                    attn_tile_proc(out1, rs10, rs11, aS1, bK + 2, bV + 2,
                                   ni + 1, m1, r01, lc, src1, src2, par);
                }
            }
#pragma unroll
            for (int t = 0; t < 2; t++) {
                float a0 = t ? rs20 : rs10, a1 = t ? rs21 : rs11;
                const float* ov = t ? out2 : out1;
                int r0 = t ? r02 : r01;
                a0 += __shfl_xor_sync(0xffffffffu, a0, 1);
                a0 += __shfl_xor_sync(0xffffffffu, a0, 2);
                a1 += __shfl_xor_sync(0xffffffffu, a1, 1);
                a1 += __shfl_xor_sync(0xffffffffu, a1, 2);
                float inv0 = rcpf(a0), inv1 = rcpf(a1);
                unsigned* d0 = As + r0 * 68 + 8 * h + 2 * lc;
                unsigned* d1 = As + (r0 + 8) * 68 + 8 * h + 2 * lc;
                d0[0] = f2tf(ov[0] * inv0); d0[1] = f2tf(ov[1] * inv0);
                d1[0] = f2tf(ov[2] * inv1); d1[1] = f2tf(ov[3] * inv1);
            }
        }
        __syncthreads();

        {
            float acc[2][4];
#pragma unroll
            for (int ni = 0; ni < 2; ni++)
#pragma unroll
                for (int e = 0; e < 4; e++) acc[ni][e] = 0.0f;
#pragma unroll
            for (int k0 = 0; k0 < 64; k0 += 8) {
                unsigned a[4];
                ldsm4(a, qkv_a + k0 * 4);
                unsigned bp[4];
                ldsm4(bp, wo_b4 + k0 * 4);
                mma_tf32(acc[0], a, bp);
                mma_tf32(acc[1], a, bp + 2);
            }
#pragma unroll
            for (int ni = 0; ni < 2; ni++) {
                int col = n0o + ni * 8 + 2 * lc;
                float2 bb = *(const float2*)(bo + col);
                float2* p0 = (float2*)(x + (row0 + m0q + lr) * 64 + col);
                float2* p1 = (float2*)(x + (row0 + m0q + lr + 8) * 64 + col);
                float2 r0v = *p0, r1v = *p1;
                r0v.x += acc[ni][0] + bb.x;
                r0v.y += acc[ni][1] + bb.y;
                r1v.x += acc[ni][2] + bb.x;
                r1v.y += acc[ni][3] + bb.y;
                *p0 = r0v;
                *p1 = r1v;
            }
        }
    }
}

// stage relu(h1 32x32 tile) as fp16 into chunk buffer (stride 72 halves).
__device__ __forceinline__ void stage_relu32h(
    __half* buf, const float acc[2][4][4], const float* __restrict__ b1,
    int gn0, int m0w, int lr, int lc) {
    const int ln0 = gn0 & 63;
#pragma unroll
    for (int mi = 0; mi < 2; mi++)
#pragma unroll
        for (int ni = 0; ni < 4; ni++) {
            int coll = ln0 + ni * 8 + 2 * lc;
            float2 bb = *(const float2*)(b1 + gn0 + ni * 8 + 2 * lc);
            int r = m0w + mi * 16 + lr;
            *(__half2*)(buf + r * 72 + coll) = __floats2half2_rn(
                fmaxf(acc[mi][ni][0] + bb.x, 0.f),
                fmaxf(acc[mi][ni][1] + bb.y, 0.f));
            *(__half2*)(buf + (r + 8) * 72 + coll) = __floats2half2_rn(
                fmaxf(acc[mi][ni][2] + bb.x, 0.f),
                fmaxf(acc[mi][ni][3] + bb.y, 0.f));
        }
}

// ---------------------------------------------------------------------------
// Persistent FFN kernel (fp16 operands, m16n8k16): LN2 + W1+ReLU (32 warps x
// 32x32) + W2 (32 warps x 16x16, staged chunks) + residual.
// MODE 2: + LNf + lm_head (fp16) + loss.
// smem (halves): Ash[128][72] | W1h[256][72] | W2h[64][264] | ext
//   MODE0: ext = As2h[128][72];  MODE2: ext = lmwh[72][72] | ls[128][66] f32
// ---------------------------------------------------------------------------
template <int MODE>
__global__ __launch_bounds__(1024) void ffn_p(
    float* __restrict__ x,
    const float* __restrict__ lng, const float* __restrict__ lnb,
    const float* __restrict__ w1, const float* __restrict__ b1,
    const float* __restrict__ w2, const float* __restrict__ b2,
    const float* __restrict__ lnfg, const float* __restrict__ lnfb,
    const float* __restrict__ lmw, const float* __restrict__ lmb,
    const int* __restrict__ tgt,
    float* __restrict__ logits, float* __restrict__ tokloss) {
    extern __shared__ unsigned sm[];
    __half* hsm = (__half*)sm;
    __half* Ash = hsm;                   // [128][72]
    __half* W1h = hsm + 9216;            // [256][72]
    __half* W2h = hsm + 27648;           // [64][264]
    __half* ext = hsm + 44544;
    __half* As2h = (MODE == 0) ? ext : ext + 5184;
    __half* lmwh = ext;                  // [72][72]  (MODE 2)
    float* ls = (float*)(ext + 5184);    // [128][66] (MODE 2)

    const int tid = threadIdx.x;
    const int wid = tid >> 5, lane = tid & 31;
    const int lr = lane >> 2, lc = lane & 3;
    const int plh8 = ((lane >> 4) & 1) * 8;      // pair row offset
    const int hkh8 = ((lane >> 3) & 1) * 8;      // k-half col offset (halves)
    const int hih8 = (lane >> 4) * 8;            // A col offset (halves)

    // ---- stage weights ONCE (fp16) ------------------------------------------
#pragma unroll
    for (int j = 0; j < 16; j++) {
        int e = tid + j * 1024;
        W1h[(e & 255) * 72 + (e >> 8)] = __float2half(w1[e]);
    }
#pragma unroll
    for (int j = 0; j < 16; j++) {
        int e = tid + j * 1024;
        W2h[(e & 63) * 264 + (e >> 6)] = __float2half(w2[e]);
    }
    if (MODE == 2) {
        if (tid < 7 * 72) lmwh[65 * 72 + tid] = __float2half(0.f);
#pragma unroll
        for (int j = 0; j < 5; j++) {
            int e = tid + j * 1024;
            if (e < 65 * 64) {
                int n = e >> 6, k = e & 63;
                lmwh[n * 72 + k] = __float2half(lmw[k * 65 + n]);
            }
        }
    }
    const float gg0 = lng[lane], gg1 = lng[lane + 32];
    const float bbl0 = lnb[lane], bbl1 = lnb[lane + 32];

    // GEMM1: 32 warps, 32x32 tiles (4 m-groups x 8 n-groups), k16 steps
    const int wm2 = wid >> 3, wn8 = wid & 7;
    const int m0w = wm2 * 32, gn0 = wn8 * 32;
    const unsigned g1a0 = s2u(Ash + (m0w + (lane & 15)) * 72 + hih8);
    const unsigned g1a1 = s2u(Ash + (m0w + 16 + (lane & 15)) * 72 + hih8);
    const unsigned g1b0 = s2u(W1h + (gn0 + plh8 + (lane & 7)) * 72 + hkh8);
    const unsigned g1b1 = s2u(W1h + (gn0 + 16 + plh8 + (lane & 7)) * 72 + hkh8);
    const int chunk_own = wn8 >> 1;

    // GEMM2: 32 warps, 16x16 tiles, k16 steps
    const int wm = wid >> 2, wn = wid & 3;
    const int m0 = wm * 16;
    const int n02 = wn * 16;
    const unsigned abase0 = s2u(Ash + (m0 + (lane & 15)) * 72 + hih8);
    const unsigned abase1 = s2u(As2h + (m0 + (lane & 15)) * 72 + hih8);
    const unsigned b2base = s2u(W2h + (n02 + plh8 + (lane & 7)) * 264 + hkh8);

    for (int b = blockIdx.x; b < NBATCH; b += PGRID) {
        const long row0 = (long)b * 128;
        __syncthreads();   // protect smem reuse across iterations

        // ---- LN2 -> Ash (fp16) ----------------------------------------------
#pragma unroll
        for (int rr = 0; rr < 4; rr++) {
            int r = wid + rr * 32;
            float a0 = x[(row0 + r) * 64 + lane];
            float a1 = x[(row0 + r) * 64 + lane + 32];
            float o0, o1;
            warp_ln_vals(a0, a1, gg0, gg1, bbl0, bbl1, o0, o1);
            Ash[r * 72 + lane] = __float2half(o0);
            Ash[r * 72 + lane + 32] = __float2half(o1);
        }
        __syncthreads();

        // ---- GEMM1 (32 warps x 32x32, fp16 k16) -------------------------------
        float acc[2][4][4];
#pragma unroll
        for (int mi = 0; mi < 2; mi++)
#pragma unroll
            for (int ni = 0; ni < 4; ni++)
#pragma unroll
                for (int e = 0; e < 4; e++) acc[mi][ni][e] = 0.0f;
#pragma unroll
        for (int k0 = 0; k0 < 64; k0 += 16) {
            unsigned a0[4], a1[4], b0[4], b1[4];
            ldsm4(a0, g1a0 + k0 * 2);
            ldsm4(a1, g1a1 + k0 * 2);
            ldsm4(b0, g1b0 + k0 * 2);
            ldsm4(b1, g1b1 + k0 * 2);
            mma_f16(acc[0][0], a0, b0);   mma_f16(acc[0][1], a0, b0 + 2);
            mma_f16(acc[0][2], a0, b1);   mma_f16(acc[0][3], a0, b1 + 2);
            mma_f16(acc[1][0], a1, b0);   mma_f16(acc[1][1], a1, b0 + 2);
            mma_f16(acc[1][2], a1, b1);   mma_f16(acc[1][3], a1, b1 + 2);
        }

        // ---- GEMM2 (32 warps x 16x16, fp16 k16), relu(h1) staged --------------
        float acc2[2][4];
#pragma unroll
        for (int ni = 0; ni < 2; ni++)
#pragma unroll
            for (int e = 0; e < 4; e++) acc2[ni][e] = 0.0f;

        if (MODE == 0) {
            __syncthreads();                     // GEMM1 reads of Ash complete
            if (chunk_own == 0) stage_relu32h(Ash, acc, b1, gn0, m0w, lr, lc);
            __syncthreads();
#pragma unroll
            for (int kc = 0; kc < 4; kc++) {
                if (kc < 3 && chunk_own == kc + 1)
                    stage_relu32h((kc & 1) ? Ash : As2h, acc, b1, gn0, m0w, lr, lc);
                unsigned ab = (kc & 1) ? abase1 : abase0;
#pragma unroll
                for (int k0 = 0; k0 < 64; k0 += 16) {
                    unsigned a[4], bp[4];
                    ldsm4(a, ab + k0 * 2);
                    ldsm4(bp, b2base + (kc * 64 + k0) * 2);
                    mma_f16(acc2[0], a, bp);
                    mma_f16(acc2[1], a, bp + 2);
                }
                if (kc < 3) __syncthreads();
            }
        } else {
#pragma unroll
            for (int kc = 0; kc < 4; kc++) {
                __syncthreads();
                if (chunk_own == kc) stage_relu32h(Ash, acc, b1, gn0, m0w, lr, lc);
                __syncthreads();
#pragma unroll
                for (int k0 = 0; k0 < 64; k0 += 16) {
                    unsigned a[4], bp[4];
                    ldsm4(a, abase0 + k0 * 2);
                    ldsm4(bp, b2base + (kc * 64 + k0) * 2);
                    mma_f16(acc2[0], a, bp);
                    mma_f16(acc2[1], a, bp + 2);
                }
            }
        }

        // ---- epilogue: + bias + residual rmw on x ---------------------------
#pragma unroll
        for (int ni = 0; ni < 2; ni++) {
            int col = n02 + ni * 8 + 2 * lc;
            float2 bb = *(const float2*)(b2 + col);
            float2* p0 = (float2*)(x + (row0 + m0 + lr) * 64 + col);
            float2* p1 = (float2*)(x + (row0 + m0 + lr + 8) * 64 + col);
            float2 r0v = *p0, r1v = *p1;
            r0v.x += acc2[ni][0] + bb.x;
            r0v.y += acc2[ni][1] + bb.y;
            r1v.x += acc2[ni][2] + bb.x;
            r1v.y += acc2[ni][3] + bb.y;
            *p0 = r0v;
            *p1 = r1v;
        }

        // ---- MODE 2: LNf + lm_head (fp16) + logits + loss -------------------
        if (MODE == 2) {
            __syncthreads();
            {
                float fg0 = lnfg[lane], fg1 = lnfg[lane + 32];
                float fb0 = lnfb[lane], fb1 = lnfb[lane + 32];
#pragma unroll
                for (int rr = 0; rr < 4; rr++) {
                    int r = wid + rr * 32;
                    float a0 = x[(row0 + r) * 64 + lane];
                    float a1 = x[(row0 + r) * 64 + lane + 32];
                    float o0, o1;
                    warp_ln_vals(a0, a1, fg0, fg1, fb0, fb1, o0, o1);
                    Ash[r * 72 + lane] = __float2half(o0);
                    Ash[r * 72 + lane + 32] = __float2half(o1);
                }
            }
            __syncthreads();

            const int mh = (wid >> 2) * 16;
            const int nq = wid & 3;
            const int nt0 = (nq == 0) ? 0 : (nq == 1) ? 3 : (nq == 2) ? 5 : 7;
            const int ntn = (nq == 0) ? 3 : 2;
            float lacc[3][4];
#pragma unroll
            for (int ni = 0; ni < 3; ni++)
#pragma unroll
                for (int e = 0; e < 4; e++) lacc[ni][e] = 0.0f;
            unsigned la = s2u(Ash + (mh + (lane & 15)) * 72 + hih8);
            unsigned lb = s2u(lmwh + (nt0 * 8 + (lane & 7)) * 72 + hkh8);
#pragma unroll
            for (int k0 = 0; k0 < 64; k0 += 16) {
                unsigned a[4];
                ldsm4(a, la + k0 * 2);
#pragma unroll
                for (int ni = 0; ni < 3; ni++) {
                    if (ni < ntn) {
                        unsigned bfr[2];
                        ldsm2(bfr, lb + (ni * 8 * 72 + k0) * 2);
                        mma_f16(lacc[ni], a, bfr);
                    }
                }
            }
#pragma unroll
            for (int ni = 0; ni < 3; ni++) {
                if (ni < ntn) {
                    int col = (nt0 + ni) * 8 + 2 * lc;
                    if (col < 65) {
                        float bb = lmb[col];
                        ls[(mh + lr) * 66 + col] = lacc[ni][0] + bb;
                        ls[(mh + lr + 8) * 66 + col] = lacc[ni][2] + bb;
                    }
                    if (col + 1 < 65) {
                        float bb = lmb[col + 1];
                        ls[(mh + lr) * 66 + col + 1] = lacc[ni][1] + bb;
                        ls[(mh + lr + 8) * 66 + col + 1] = lacc[ni][3] + bb;
                    }
                }
            }
            __syncthreads();

            for (int i = tid; i < 128 * 65; i += 1024) {
                int r = i / 65, c = i - r * 65;
                logits[row0 * 65 + i] = ls[r * 66 + c];
            }
#pragma unroll
            for (int rr = 0; rr < 4; rr++) {
                int t = wid * 4 + rr;
                float v0 = ls[t * 66 + lane];
                float v1 = ls[t * 66 + lane + 32];
                float v2 = (lane == 0) ? ls[t * 66 + 64] : -1e30f;
                float mx = fmaxf(fmaxf(v0, v1), v2);
#pragma unroll
                for (int o = 16; o; o >>= 1)
                    mx = fmaxf(mx, __shfl_xor_sync(0xffffffffu, mx, o));
                float se = __expf(v0 - mx) + __expf(v1 - mx) + __expf(v2 - mx);
#pragma unroll
                for (int o = 16; o; o >>= 1)
                    se += __shfl_xor_sync(0xffffffffu, se, o);
                if (lane == 0) {
                    int tg = tgt[row0 + t];
                    tokloss[row0 + t] = -(ls[t * 66 + tg] - mx - __logf(se));
                }
            }
        }
    }
}

// ---------------------------------------------------------------------------
__global__ void reduce1_kernel(const float* __restrict__ tl,
                               double* __restrict__ part) {
    __shared__ double smd[256];
    long base = (long)blockIdx.x * (NTOK / 512);
    double s = 0.0;
    for (int i = threadIdx.x; i < NTOK / 512; i += 256) s += (double)tl[base + i];
    smd[threadIdx.x] = s;
    __syncthreads();
    for (int o = 128; o; o >>= 1) {
        if (threadIdx.x < o) smd[threadIdx.x] += smd[threadIdx.x + o];
        __syncthreads();
    }
    if (threadIdx.x == 0) part[blockIdx.x] = smd[0];
}

__global__ void reduce2_kernel(const double* __restrict__ part,
                               float* __restrict__ out) {
    __shared__ double smd[512];
    smd[threadIdx.x] = part[threadIdx.x];
    __syncthreads();
    for (int o = 256; o; o >>= 1) {
        if (threadIdx.x < o) smd[threadIdx.x] += smd[threadIdx.x + o];
        __syncthreads();
    }
    if (threadIdx.x == 0) out[0] = (float)(smd[0] / (double)NTOK);
}

// ---------------------------------------------------------------------------
extern "C" void kernel_launch(void* const* d_in, const int* in_sizes, int n_in,
                              void* d_out, int out_size) {
    const float* tok_emb = (const float*)d_in[0];
    const float* pos_emb = (const float*)d_in[1];
    const float* ln1_g   = (const float*)d_in[2];
    const float* ln1_b   = (const float*)d_in[3];
    const float* wq      = (const float*)d_in[4];
    const float* wk      = (const float*)d_in[5];
    const float* wv      = (const float*)d_in[6];
    const float* wo      = (const float*)d_in[7];
    const float* bo      = (const float*)d_in[8];
    const float* ln2_g   = (const float*)d_in[9];
    const float* ln2_b   = (const float*)d_in[10];
    const float* w1      = (const float*)d_in[11];
    const float* b1      = (const float*)d_in[12];
    const float* w2      = (const float*)d_in[13];
    const float* b2      = (const float*)d_in[14];
    const float* lnf_g   = (const float*)d_in[15];
    const float* lnf_b   = (const float*)d_in[16];
    const float* lm_w    = (const float*)d_in[17];
    const float* lm_b    = (const float*)d_in[18];
    const int*   idx     = (const int*)d_in[19];
    const int*   targets = (const int*)d_in[20];

    float *x, *lg, *tl;
    double* part;
    cudaGetSymbolAddress((void**)&x,  g_x);
    cudaGetSymbolAddress((void**)&lg, g_logits);
    cudaGetSymbolAddress((void**)&tl, g_tokloss);
    cudaGetSymbolAddress((void**)&part, g_partial);

    float* outp = (float*)d_out;
    const long LSZ = (long)NTOK * NVOCAB;
    float* logits = ((long)out_size >= LSZ) ? outp : lg;
    float* lossp;
    if ((long)out_size >= LSZ + 1)      lossp = outp + LSZ;
    else if (out_size == 1)             lossp = outp;
    else                                lossp = tl;

    const int ATTN_SMEM = 51968 * 4;                 // 207872 B
    const int FFN_SMEM  = (44544 + 9216) * 2;        // 107520 B
    const int FFN2_SMEM = (44544 + 5184) * 2 + 128 * 66 * 4;  // 133248 B
    cudaFuncSetAttribute(attn_p<0>, cudaFuncAttributeMaxDynamicSharedMemorySize, ATTN_SMEM);
    cudaFuncSetAttribute(attn_p<1>, cudaFuncAttributeMaxDynamicSharedMemorySize, ATTN_SMEM);
    cudaFuncSetAttribute(ffn_p<0>,  cudaFuncAttributeMaxDynamicSharedMemorySize, FFN_SMEM);
    cudaFuncSetAttribute(ffn_p<2>,  cudaFuncAttributeMaxDynamicSharedMemorySize, FFN2_SMEM);

    for (int l = 0; l < NLAYER; l++) {
        if (l == 0) {
            attn_p<1><<<PGRID, 1024, ATTN_SMEM>>>(
                x, idx, tok_emb, pos_emb, ln1_g, ln1_b,
                wq, wk, wv, wo, bo);
        } else {
            attn_p<0><<<PGRID, 1024, ATTN_SMEM>>>(
                x, idx, tok_emb, pos_emb,
                ln1_g + l * 64, ln1_b + l * 64,
                wq + (long)l * 4096, wk + (long)l * 4096, wv + (long)l * 4096,
                wo + (long)l * 4096, bo + l * 64);
        }
        if (l < NLAYER - 1) {
            ffn_p<0><<<PGRID, 1024, FFN_SMEM>>>(
                x, ln2_g + l * 64, ln2_b + l * 64,
                w1 + (long)l * 64 * 256, b1 + l * 256,
                w2 + (long)l * 256 * 64, b2 + l * 64,
                lnf_g, lnf_b, lm_w, lm_b, targets, logits, tl);
        } else {
            ffn_p<2><<<PGRID, 1024, FFN2_SMEM>>>(
                x, ln2_g + l * 64, ln2_b + l * 64,
                w1 + (long)l * 64 * 256, b1 + l * 256,
                w2 + (long)l * 256 * 64, b2 + l * 64,
                lnf_g, lnf_b, lm_w, lm_b, targets, logits, tl);
        }
    }
    reduce1_kernel<<<512, 256>>>(tl, part);
    reduce2_kernel<<<1, 512>>>(part, lossp);
}

// round 17
// speedup vs baseline: 1.5068x; 1.2089x over previous
#include <cuda_runtime.h>
#include <cuda_fp16.h>
#include <cstdint>

// ---------------------------------------------------------------------------
// 3-layer transformer forward. B=4096, T=128, D=64, H=8, HD=8, DF=256, V=65.
// Round 17: attention kernel converted to fp16 (m16n8k16 for QKV/Wo,
// m16n8k8 for S/PV). f16 A-fragment layout == S C-fragment layout, so the
// P handoff is just two f16x2 packs (no shuffles). FFN kernels = R16.
// ---------------------------------------------------------------------------

#define NTOK (4096 * 128)
#define NBATCH 4096
#define TSEQ 128
#define DMODEL 64
#define NVOCAB 65
#define NHEAD 8
#define DFF 256
#define NLAYER 3
#define PGRID 152

__device__ float g_x[(size_t)NTOK * DMODEL];
__device__ float g_logits[(size_t)NTOK * NVOCAB];
__device__ float g_tokloss[NTOK];
__device__ double g_partial[512];

// ---------------------------------------------------------------------------
__device__ __forceinline__ float ex2f(float f) {
    float r;
    asm("ex2.approx.f32 %0, %1;" : "=f"(r) : "f"(f));
    return r;
}

__device__ __forceinline__ float rcpf(float f) {
    float r;
    asm("rcp.approx.f32 %0, %1;" : "=f"(r) : "f"(f));
    return r;
}

__device__ __forceinline__ unsigned s2u(const void* p) {
    return (unsigned)__cvta_generic_to_shared(p);
}

__device__ __forceinline__ unsigned packh2(float lo, float hi) {
    unsigned r;
    asm("cvt.rn.f16x2.f32 %0, %1, %2;" : "=r"(r) : "f"(hi), "f"(lo));
    return r;
}

__device__ __forceinline__ void ldsm4(unsigned* d, unsigned addr) {
    asm volatile(
        "ldmatrix.sync.aligned.m8n8.x4.shared.b16 {%0,%1,%2,%3}, [%4];"
        : "=r"(d[0]), "=r"(d[1]), "=r"(d[2]), "=r"(d[3]) : "r"(addr));
}

__device__ __forceinline__ void ldsm2(unsigned* d, unsigned addr) {
    asm volatile(
        "ldmatrix.sync.aligned.m8n8.x2.shared.b16 {%0,%1}, [%2];"
        : "=r"(d[0]), "=r"(d[1]) : "r"(addr));
}

__device__ __forceinline__ void mma_f16(float* c, const unsigned* a,
                                        const unsigned* b) {
    asm volatile(
        "mma.sync.aligned.m16n8k16.row.col.f32.f16.f16.f32 "
        "{%0,%1,%2,%3},{%4,%5,%6,%7},{%8,%9},{%0,%1,%2,%3};"
        : "+f"(c[0]), "+f"(c[1]), "+f"(c[2]), "+f"(c[3])
        : "r"(a[0]), "r"(a[1]), "r"(a[2]), "r"(a[3]), "r"(b[0]), "r"(b[1]));
}

__device__ __forceinline__ void mma_f16k8(float* c, const unsigned* a,
                                          unsigned b) {
    asm volatile(
        "mma.sync.aligned.m16n8k8.row.col.f32.f16.f16.f32 "
        "{%0,%1,%2,%3},{%4,%5},{%6},{%0,%1,%2,%3};"
        : "+f"(c[0]), "+f"(c[1]), "+f"(c[2]), "+f"(c[3])
        : "r"(a[0]), "r"(a[1]), "r"(b));
}

__device__ __forceinline__ void warp_ln_vals(float a0, float a1,
                                             float gg0, float gg1,
                                             float bb0, float bb1,
                                             float& o0, float& o1) {
    float s = a0 + a1;
#pragma unroll
    for (int o = 16; o; o >>= 1) s += __shfl_xor_sync(0xffffffffu, s, o);
    float mu = s * (1.0f / 64.0f);
    float d0 = a0 - mu, d1 = a1 - mu;
    float vs = d0 * d0 + d1 * d1;
#pragma unroll
    for (int o = 16; o; o >>= 1) vs += __shfl_xor_sync(0xffffffffu, vs, o);
    float inv = rsqrtf(vs * (1.0f / 64.0f) + 1e-5f);
    o0 = d0 * inv * gg0 + bb0;
    o1 = d1 * inv * gg1 + bb1;
}

// One attention k-tile (fp16): S-MMA (k8), ex2+mask, rowsum, pack P directly
// into f16 A-fragment (layouts coincide), PV-MMA (k8).
__device__ __forceinline__ void attn_tile_f16(
    float* out, float& rs0, float& rs1,
    const unsigned* aS, unsigned bK, unsigned bV,
    int ni, int m, int r0, int lc) {
    float c[4] = {0.f, 0.f, 0.f, 0.f};
    mma_f16k8(c, aS, bK);
    if (8 * ni + 7 <= 16 * m) {
        c[0] = ex2f(c[0]); c[1] = ex2f(c[1]);
        c[2] = ex2f(c[2]); c[3] = ex2f(c[3]);
    } else {
        int j0 = 8 * ni + 2 * lc, j1 = j0 + 1;
        c[0] = (j0 <= r0) ? ex2f(c[0]) : 0.f;
        c[1] = (j1 <= r0) ? ex2f(c[1]) : 0.f;
        c[2] = (j0 <= r0 + 8) ? ex2f(c[2]) : 0.f;
        c[3] = (j1 <= r0 + 8) ? ex2f(c[3]) : 0.f;
    }
    rs0 += c[0] + c[1];
    rs1 += c[2] + c[3];
    unsigned aP[2];
    aP[0] = packh2(c[0], c[1]);
    aP[1] = packh2(c[2], c[3]);
    mma_f16k8(out, aP, bV);
}

// ---------------------------------------------------------------------------
// Persistent attention kernel, full fp16. EMB=1: embed fused (layer 0).
// smem (halves): Ash[128][72] | qsh[128][72] | ksh[128][72] | vsT[64][136] |
//                Wsh[192][72] | Wosh[64][72]  = 54784 halves = 109568 B.
// ---------------------------------------------------------------------------
template <int EMB>
__global__ __launch_bounds__(1024) void attn_p(
    float* __restrict__ x,
    const int* __restrict__ idx, const float* __restrict__ te,
    const float* __restrict__ pe,
    const float* __restrict__ lng, const float* __restrict__ lnb,
    const float* __restrict__ wq, const float* __restrict__ wk,
    const float* __restrict__ wv, const float* __restrict__ wo,
    const float* __restrict__ bo) {
    extern __shared__ unsigned sm[];
    __half* hsm = (__half*)sm;
    __half* Ash = hsm;                   // [128][72]
    __half* qsh = hsm + 9216;            // [128][72]
    __half* ksh = qsh + 9216;            // [128][72]
    __half* vsT = ksh + 9216;            // [64][136]
    __half* Wsh = vsT + 8704;            // [192][72]
    __half* Wosh = Wsh + 13824;          // [64][72]

    const int tid = threadIdx.x;
    const int wid = tid >> 5, lane = tid & 31;
    const int lr = lane >> 2, lc = lane & 3;
    const int plh8 = ((lane >> 4) & 1) * 8;      // B pair row offset
    const int hkh8 = ((lane >> 3) & 1) * 8;      // B k-half col offset (halves)
    const int hih8 = (lane >> 4) * 8;            // A col offset (halves)

    // ---- stage weights ONCE (fp16) ------------------------------------------
    {
        const float* wsrc[3] = {wq, wk, wv};
#pragma unroll
        for (int s = 0; s < 3; s++) {
            const float* W = wsrc[s];
#pragma unroll
            for (int j = 0; j < 4; j++) {
                int e = tid + j * 1024;          // e = k*64 + n
                Wsh[(s * 64 + (e & 63)) * 72 + (e >> 6)] = __float2half(W[e]);
            }
        }
#pragma unroll
        for (int j = 0; j < 4; j++) {
            int e = tid + j * 1024;              // e = k*64 + n
            Wosh[(e & 63) * 72 + (e >> 6)] = __float2half(wo[e]);
        }
    }
    const float gg0 = lng[lane], gg1 = lng[lane + 32];
    const float bbl0 = lnb[lane], bbl1 = lnb[lane + 32];

    // hoisted fragment base addresses
    const int wm = wid >> 2, wn = wid & 3;
    const int m0q = wm * 16, n0q = wn * 48;
    const unsigned qkv_a = s2u(Ash + (m0q + (lane & 15)) * 72 + hih8);
    const unsigned qkv_b = s2u(Wsh + (n0q + plh8 + (lane & 7)) * 72 + hkh8);
    const int h = wid & 7;
    const int mb = wid >> 3;
    const int m1 = mb, m2 = 7 - mb;
    const int nt1 = 2 * m1 + 2, nt2 = 2 * m2 + 2;
    const int r01 = 16 * m1 + lr, r02 = 16 * m2 + lr;
    const unsigned aS1a = s2u(qsh + (16 * m1 + (lane & 15)) * 72 + 8 * h);
    const unsigned aS2a = s2u(qsh + (16 * m2 + (lane & 15)) * 72 + 8 * h);
    const unsigned kb = s2u(ksh + (lane & 15) * 72 + 8 * h);
    const unsigned vb = s2u(vsT + (8 * h + (lane & 7)) * 136 + ((lane >> 3) & 1) * 8);
    const int n0o = wn * 16;
    const unsigned wo_b = s2u(Wosh + (n0o + plh8 + (lane & 7)) * 72 + hkh8);

    for (int b = blockIdx.x; b < NBATCH; b += PGRID) {
        const long row0 = (long)b * 128;
        __syncthreads();   // protect smem reuse across iterations

        // ---- LN1 -> Ash (fp16); EMB: compute embed + write residual x -------
#pragma unroll
        for (int rr = 0; rr < 4; rr++) {
            int r = wid + rr * 32;
            float a0, a1;
            if (EMB) {
                int id = idx[row0 + r];
                a0 = te[id * 64 + lane] + pe[r * 64 + lane];
                a1 = te[id * 64 + lane + 32] + pe[r * 64 + lane + 32];
                x[(row0 + r) * 64 + lane] = a0;
                x[(row0 + r) * 64 + lane + 32] = a1;
            } else {
                a0 = x[(row0 + r) * 64 + lane];
                a1 = x[(row0 + r) * 64 + lane + 32];
            }
            float o0, o1;
            warp_ln_vals(a0, a1, gg0, gg1, bbl0, bbl1, o0, o1);
            Ash[r * 72 + lane] = __float2half(o0);
            Ash[r * 72 + lane + 32] = __float2half(o1);
        }
        __syncthreads();

        // ---- QKV MMA (fp16 k16, warp 16x48) -> qsh, ksh, vsT ----------------
        {
            float acc[6][4];
#pragma unroll
            for (int ni = 0; ni < 6; ni++)
#pragma unroll
                for (int e = 0; e < 4; e++) acc[ni][e] = 0.0f;
#pragma unroll
            for (int k0 = 0; k0 < 64; k0 += 16) {
                unsigned a[4];
                ldsm4(a, qkv_a + k0 * 2);
#pragma unroll
                for (int p = 0; p < 3; p++) {
                    unsigned bp[4];
                    ldsm4(bp, qkv_b + (p * 16 * 72 + k0) * 2);
                    mma_f16(acc[2 * p], a, bp);
                    mma_f16(acc[2 * p + 1], a, bp + 2);
                }
            }
#pragma unroll
            for (int ni = 0; ni < 6; ni++) {
                int cg = n0q + ni * 8;
                if (cg < 64) {     // q, pre-scaled by log2e/sqrt(8) for ex2
                    const float sc = 0.35355339059327373f * 1.4426950408889634f;
                    int col = cg + 2 * lc;
                    *(unsigned*)(qsh + (m0q + lr) * 72 + col) =
                        packh2(acc[ni][0] * sc, acc[ni][1] * sc);
                    *(unsigned*)(qsh + (m0q + lr + 8) * 72 + col) =
                        packh2(acc[ni][2] * sc, acc[ni][3] * sc);
                } else if (cg < 128) {               // k
                    int col = cg - 64 + 2 * lc;
                    *(unsigned*)(ksh + (m0q + lr) * 72 + col) =
                        packh2(acc[ni][0], acc[ni][1]);
                    *(unsigned*)(ksh + (m0q + lr + 8) * 72 + col) =
                        packh2(acc[ni][2], acc[ni][3]);
                } else {                             // v, transposed
                    int hd = cg - 128 + 2 * lc;
                    vsT[hd * 136 + m0q + lr]           = __float2half(acc[ni][0]);
                    vsT[(hd + 1) * 136 + m0q + lr]     = __float2half(acc[ni][1]);
                    vsT[hd * 136 + m0q + lr + 8]       = __float2half(acc[ni][2]);
                    vsT[(hd + 1) * 136 + m0q + lr + 8] = __float2half(acc[ni][3]);
                }
            }
        }
        __syncthreads();

        // ---- fp16 MMA attention (fused pair, no shuffles) -> Ash ------------
        {
            unsigned aS1[2], aS2[2];
            ldsm2(aS1, aS1a);
            ldsm2(aS2, aS2a);
            float out1[4] = {0.f, 0.f, 0.f, 0.f}, out2[4] = {0.f, 0.f, 0.f, 0.f};
            float rs10 = 0.f, rs11 = 0.f, rs20 = 0.f, rs21 = 0.f;
            unsigned kaddr = kb, vaddr = vb;
            for (int ni = 0; ni < nt2; ni += 2) {
                unsigned bK[2], bV[2];
                ldsm2(bK, kaddr);      // two key tiles (8 keys each)
                ldsm2(bV, vaddr);      // matching V tiles
                kaddr += 16 * 72 * 2;  // +16 key rows (bytes)
                vaddr += 16 * 2;       // +16 key cols  (bytes)
                attn_tile_f16(out2, rs20, rs21, aS2, bK[0], bV[0], ni, m2, r02, lc);
                attn_tile_f16(out2, rs20, rs21, aS2, bK[1], bV[1], ni + 1, m2, r02, lc);
                if (ni < nt1) {
                    attn_tile_f16(out1, rs10, rs11, aS1, bK[0], bV[0], ni, m1, r01, lc);
                    attn_tile_f16(out1, rs10, rs11, aS1, bK[1], bV[1], ni + 1, m1, r01, lc);
                }
            }
#pragma unroll
            for (int t = 0; t < 2; t++) {
                float a0 = t ? rs20 : rs10, a1 = t ? rs21 : rs11;
                const float* ov = t ? out2 : out1;
                int r0 = t ? r02 : r01;
                a0 += __shfl_xor_sync(0xffffffffu, a0, 1);
                a0 += __shfl_xor_sync(0xffffffffu, a0, 2);
                a1 += __shfl_xor_sync(0xffffffffu, a1, 1);
                a1 += __shfl_xor_sync(0xffffffffu, a1, 2);
                float inv0 = rcpf(a0), inv1 = rcpf(a1);
                *(unsigned*)(Ash + r0 * 72 + 8 * h + 2 * lc) =
                    packh2(ov[0] * inv0, ov[1] * inv0);
                *(unsigned*)(Ash + (r0 + 8) * 72 + 8 * h + 2 * lc) =
                    packh2(ov[2] * inv1, ov[3] * inv1);
            }
        }
        __syncthreads();

        // ---- Wo MMA (fp16 k16, 16x16) + bias + residual rmw on x ------------
        {
            float acc[2][4];
#pragma unroll
            for (int ni = 0; ni < 2; ni++)
#pragma unroll
                for (int e = 0; e < 4; e++) acc[ni][e] = 0.0f;
#pragma unroll
            for (int k0 = 0; k0 < 64; k0 += 16) {
                unsigned a[4], bp[4];
                ldsm4(a, qkv_a + k0 * 2);   // Ash, same m-tile as QKV
                ldsm4(bp, wo_b + k0 * 2);
                mma_f16(acc[0], a, bp);
                mma_f16(acc[1], a, bp + 2);
            }
#pragma unroll
            for (int ni = 0; ni < 2; ni++) {
                int col = n0o + ni * 8 + 2 * lc;
                float2 bb = *(const float2*)(bo + col);
                float2* p0 = (float2*)(x + (row0 + m0q + lr) * 64 + col);
                float2* p1 = (float2*)(x + (row0 + m0q + lr + 8) * 64 + col);
                float2 r0v = *p0, r1v = *p1;
                r0v.x += acc[ni][0] + bb.x;
                r0v.y += acc[ni][1] + bb.y;
                r1v.x += acc[ni][2] + bb.x;
                r1v.y += acc[ni][3] + bb.y;
                *p0 = r0v;
                *p1 = r1v;
            }
        }
    }
}

// stage relu(h1 32x32 tile) as fp16 into chunk buffer (stride 72 halves).
__device__ __forceinline__ void stage_relu32h(
    __half* buf, const float acc[2][4][4], const float* __restrict__ b1,
    int gn0, int m0w, int lr, int lc) {
    const int ln0 = gn0 & 63;
#pragma unroll
    for (int mi = 0; mi < 2; mi++)
#pragma unroll
        for (int ni = 0; ni < 4; ni++) {
            int coll = ln0 + ni * 8 + 2 * lc;
            float2 bb = *(const float2*)(b1 + gn0 + ni * 8 + 2 * lc);
            int r = m0w + mi * 16 + lr;
            *(__half2*)(buf + r * 72 + coll) = __floats2half2_rn(
                fmaxf(acc[mi][ni][0] + bb.x, 0.f),
                fmaxf(acc[mi][ni][1] + bb.y, 0.f));
            *(__half2*)(buf + (r + 8) * 72 + coll) = __floats2half2_rn(
                fmaxf(acc[mi][ni][2] + bb.x, 0.f),
                fmaxf(acc[mi][ni][3] + bb.y, 0.f));
        }
}

// ---------------------------------------------------------------------------
// Persistent FFN kernel (fp16, R16 verbatim). MODE 2: + LNf + lm_head + loss.
// ---------------------------------------------------------------------------
template <int MODE>
__global__ __launch_bounds__(1024) void ffn_p(
    float* __restrict__ x,
    const float* __restrict__ lng, const float* __restrict__ lnb,
    const float* __restrict__ w1, const float* __restrict__ b1,
    const float* __restrict__ w2, const float* __restrict__ b2,
    const float* __restrict__ lnfg, const float* __restrict__ lnfb,
    const float* __restrict__ lmw, const float* __restrict__ lmb,
    const int* __restrict__ tgt,
    float* __restrict__ logits, float* __restrict__ tokloss) {
    extern __shared__ unsigned sm[];
    __half* hsm = (__half*)sm;
    __half* Ash = hsm;                   // [128][72]
    __half* W1h = hsm + 9216;            // [256][72]
    __half* W2h = hsm + 27648;           // [64][264]
    __half* ext = hsm + 44544;
    __half* As2h = (MODE == 0) ? ext : ext + 5184;
    __half* lmwh = ext;                  // [72][72]  (MODE 2)
    float* ls = (float*)(ext + 5184);    // [128][66] (MODE 2)

    const int tid = threadIdx.x;
    const int wid = tid >> 5, lane = tid & 31;
    const int lr = lane >> 2, lc = lane & 3;
    const int plh8 = ((lane >> 4) & 1) * 8;
    const int hkh8 = ((lane >> 3) & 1) * 8;
    const int hih8 = (lane >> 4) * 8;

#pragma unroll
    for (int j = 0; j < 16; j++) {
        int e = tid + j * 1024;
        W1h[(e & 255) * 72 + (e >> 8)] = __float2half(w1[e]);
    }
#pragma unroll
    for (int j = 0; j < 16; j++) {
        int e = tid + j * 1024;
        W2h[(e & 63) * 264 + (e >> 6)] = __float2half(w2[e]);
    }
    if (MODE == 2) {
        if (tid < 7 * 72) lmwh[65 * 72 + tid] = __float2half(0.f);
#pragma unroll
        for (int j = 0; j < 5; j++) {
            int e = tid + j * 1024;
            if (e < 65 * 64) {
                int n = e >> 6, k = e & 63;
                lmwh[n * 72 + k] = __float2half(lmw[k * 65 + n]);
            }
        }
    }
    const float gg0 = lng[lane], gg1 = lng[lane + 32];
    const float bbl0 = lnb[lane], bbl1 = lnb[lane + 32];

    const int wm2 = wid >> 3, wn8 = wid & 7;
    const int m0w = wm2 * 32, gn0 = wn8 * 32;
    const unsigned g1a0 = s2u(Ash + (m0w + (lane & 15)) * 72 + hih8);
    const unsigned g1a1 = s2u(Ash + (m0w + 16 + (lane & 15)) * 72 + hih8);
    const unsigned g1b0 = s2u(W1h + (gn0 + plh8 + (lane & 7)) * 72 + hkh8);
    const unsigned g1b1 = s2u(W1h + (gn0 + 16 + plh8 + (lane & 7)) * 72 + hkh8);
    const int chunk_own = wn8 >> 1;

    const int wm = wid >> 2, wn = wid & 3;
    const int m0 = wm * 16;
    const int n02 = wn * 16;
    const unsigned abase0 = s2u(Ash + (m0 + (lane & 15)) * 72 + hih8);
    const unsigned abase1 = s2u(As2h + (m0 + (lane & 15)) * 72 + hih8);
    const unsigned b2base = s2u(W2h + (n02 + plh8 + (lane & 7)) * 264 + hkh8);

    for (int b = blockIdx.x; b < NBATCH; b += PGRID) {
        const long row0 = (long)b * 128;
        __syncthreads();

#pragma unroll
        for (int rr = 0; rr < 4; rr++) {
            int r = wid + rr * 32;
            float a0 = x[(row0 + r) * 64 + lane];
            float a1 = x[(row0 + r) * 64 + lane + 32];
            float o0, o1;
            warp_ln_vals(a0, a1, gg0, gg1, bbl0, bbl1, o0, o1);
            Ash[r * 72 + lane] = __float2half(o0);
            Ash[r * 72 + lane + 32] = __float2half(o1);
        }
        __syncthreads();

        float acc[2][4][4];
#pragma unroll
        for (int mi = 0; mi < 2; mi++)
#pragma unroll
            for (int ni = 0; ni < 4; ni++)
#pragma unroll
                for (int e = 0; e < 4; e++) acc[mi][ni][e] = 0.0f;
#pragma unroll
        for (int k0 = 0; k0 < 64; k0 += 16) {
            unsigned a0[4], a1[4], b0[4], b1r[4];
            ldsm4(a0, g1a0 + k0 * 2);
            ldsm4(a1, g1a1 + k0 * 2);
            ldsm4(b0, g1b0 + k0 * 2);
            ldsm4(b1r, g1b1 + k0 * 2);
            mma_f16(acc[0][0], a0, b0);   mma_f16(acc[0][1], a0, b0 + 2);
            mma_f16(acc[0][2], a0, b1r);  mma_f16(acc[0][3], a0, b1r + 2);
            mma_f16(acc[1][0], a1, b0);   mma_f16(acc[1][1], a1, b0 + 2);
            mma_f16(acc[1][2], a1, b1r);  mma_f16(acc[1][3], a1, b1r + 2);
        }

        float acc2[2][4];
#pragma unroll
        for (int ni = 0; ni < 2; ni++)
#pragma unroll
            for (int e = 0; e < 4; e++) acc2[ni][e] = 0.0f;

        if (MODE == 0) {
            __syncthreads();
            if (chunk_own == 0) stage_relu32h(Ash, acc, b1, gn0, m0w, lr, lc);
            __syncthreads();
#pragma unroll
            for (int kc = 0; kc < 4; kc++) {
                if (kc < 3 && chunk_own == kc + 1)
                    stage_relu32h((kc & 1) ? Ash : As2h, acc, b1, gn0, m0w, lr, lc);
                unsigned ab = (kc & 1) ? abase1 : abase0;
#pragma unroll
                for (int k0 = 0; k0 < 64; k0 += 16) {
                    unsigned a[4], bp[4];
                    ldsm4(a, ab + k0 * 2);
                    ldsm4(bp, b2base + (kc * 64 + k0) * 2);
                    mma_f16(acc2[0], a, bp);
                    mma_f16(acc2[1], a, bp + 2);
                }
                if (kc < 3) __syncthreads();
            }
        } else {
#pragma unroll
            for (int kc = 0; kc < 4; kc++) {
                __syncthreads();
                if (chunk_own == kc) stage_relu32h(Ash, acc, b1, gn0, m0w, lr, lc);
                __syncthreads();
#pragma unroll
                for (int k0 = 0; k0 < 64; k0 += 16) {
                    unsigned a[4], bp[4];
                    ldsm4(a, abase0 + k0 * 2);
                    ldsm4(bp, b2base + (kc * 64 + k0) * 2);
                    mma_f16(acc2[0], a, bp);
                    mma_f16(acc2[1], a, bp + 2);
                }
            }
        }

#pragma unroll
        for (int ni = 0; ni < 2; ni++) {
            int col = n02 + ni * 8 + 2 * lc;
            float2 bb = *(const float2*)(b2 + col);
            float2* p0 = (float2*)(x + (row0 + m0 + lr) * 64 + col);
            float2* p1 = (float2*)(x + (row0 + m0 + lr + 8) * 64 + col);
            float2 r0v = *p0, r1v = *p1;
            r0v.x += acc2[ni][0] + bb.x;
            r0v.y += acc2[ni][1] + bb.y;
            r1v.x += acc2[ni][2] + bb.x;
            r1v.y += acc2[ni][3] + bb.y;
            *p0 = r0v;
            *p1 = r1v;
        }

        if (MODE == 2) {
            __syncthreads();
            {
                float fg0 = lnfg[lane], fg1 = lnfg[lane + 32];
                float fb0 = lnfb[lane], fb1 = lnfb[lane + 32];
#pragma unroll
                for (int rr = 0; rr < 4; rr++) {
                    int r = wid + rr * 32;
                    float a0 = x[(row0 + r) * 64 + lane];
                    float a1 = x[(row0 + r) * 64 + lane + 32];
                    float o0, o1;
                    warp_ln_vals(a0, a1, fg0, fg1, fb0, fb1, o0, o1);
                    Ash[r * 72 + lane] = __float2half(o0);
                    Ash[r * 72 + lane + 32] = __float2half(o1);
                }
            }
            __syncthreads();

            const int mh = (wid >> 2) * 16;
            const int nq = wid & 3;
            const int nt0 = (nq == 0) ? 0 : (nq == 1) ? 3 : (nq == 2) ? 5 : 7;
            const int ntn = (nq == 0) ? 3 : 2;
            float lacc[3][4];
#pragma unroll
            for (int ni = 0; ni < 3; ni++)
#pragma unroll
                for (int e = 0; e < 4; e++) lacc[ni][e] = 0.0f;
            unsigned la = s2u(Ash + (mh + (lane & 15)) * 72 + hih8);
            unsigned lb = s2u(lmwh + (nt0 * 8 + (lane & 7)) * 72 + hkh8);
#pragma unroll
            for (int k0 = 0; k0 < 64; k0 += 16) {
                unsigned a[4];
                ldsm4(a, la + k0 * 2);
#pragma unroll
                for (int ni = 0; ni < 3; ni++) {
                    if (ni < ntn) {
                        unsigned bfr[2];
                        ldsm2(bfr, lb + (ni * 8 * 72 + k0) * 2);
                        mma_f16(lacc[ni], a, bfr);
                    }
                }
            }
#pragma unroll
            for (int ni = 0; ni < 3; ni++) {
                if (ni < ntn) {
                    int col = (nt0 + ni) * 8 + 2 * lc;
                    if (col < 65) {
                        float bb = lmb[col];
                        ls[(mh + lr) * 66 + col] = lacc[ni][0] + bb;
                        ls[(mh + lr + 8) * 66 + col] = lacc[ni][2] + bb;
                    }
                    if (col + 1 < 65) {
                        float bb = lmb[col + 1];
                        ls[(mh + lr) * 66 + col + 1] = lacc[ni][1] + bb;
                        ls[(mh + lr + 8) * 66 + col + 1] = lacc[ni][3] + bb;
                    }
                }
            }
            __syncthreads();

            for (int i = tid; i < 128 * 65; i += 1024) {
                int r = i / 65, c = i - r * 65;
                logits[row0 * 65 + i] = ls[r * 66 + c];
            }
#pragma unroll
            for (int rr = 0; rr < 4; rr++) {
                int t = wid * 4 + rr;
                float v0 = ls[t * 66 + lane];
                float v1 = ls[t * 66 + lane + 32];
                float v2 = (lane == 0) ? ls[t * 66 + 64] : -1e30f;
                float mx = fmaxf(fmaxf(v0, v1), v2);
#pragma unroll
                for (int o = 16; o; o >>= 1)
                    mx = fmaxf(mx, __shfl_xor_sync(0xffffffffu, mx, o));
                float se = __expf(v0 - mx) + __expf(v1 - mx) + __expf(v2 - mx);
#pragma unroll
                for (int o = 16; o; o >>= 1)
                    se += __shfl_xor_sync(0xffffffffu, se, o);
                if (lane == 0) {
                    int tg = tgt[row0 + t];
                    tokloss[row0 + t] = -(ls[t * 66 + tg] - mx - __logf(se));
                }
            }
        }
    }
}

// ---------------------------------------------------------------------------
__global__ void reduce1_kernel(const float* __restrict__ tl,
                               double* __restrict__ part) {
    __shared__ double smd[256];
    long base = (long)blockIdx.x * (NTOK / 512);
    double s = 0.0;
    for (int i = threadIdx.x; i < NTOK / 512; i += 256) s += (double)tl[base + i];
    smd[threadIdx.x] = s;
    __syncthreads();
    for (int o = 128; o; o >>= 1) {
        if (threadIdx.x < o) smd[threadIdx.x] += smd[threadIdx.x + o];
        __syncthreads();
    }
    if (threadIdx.x == 0) part[blockIdx.x] = smd[0];
}

__global__ void reduce2_kernel(const double* __restrict__ part,
                               float* __restrict__ out) {
    __shared__ double smd[512];
    smd[threadIdx.x] = part[threadIdx.x];
    __syncthreads();
    for (int o = 256; o; o >>= 1) {
        if (threadIdx.x < o) smd[threadIdx.x] += smd[threadIdx.x + o];
        __syncthreads();
    }
    if (threadIdx.x == 0) out[0] = (float)(smd[0] / (double)NTOK);
}

// ---------------------------------------------------------------------------
extern "C" void kernel_launch(void* const* d_in, const int* in_sizes, int n_in,
                              void* d_out, int out_size) {
    const float* tok_emb = (const float*)d_in[0];
    const float* pos_emb = (const float*)d_in[1];
    const float* ln1_g   = (const float*)d_in[2];
    const float* ln1_b   = (const float*)d_in[3];
    const float* wq      = (const float*)d_in[4];
    const float* wk      = (const float*)d_in[5];
    const float* wv      = (const float*)d_in[6];
    const float* wo      = (const float*)d_in[7];
    const float* bo      = (const float*)d_in[8];
    const float* ln2_g   = (const float*)d_in[9];
    const float* ln2_b   = (const float*)d_in[10];
    const float* w1      = (const float*)d_in[11];
    const float* b1      = (const float*)d_in[12];
    const float* w2      = (const float*)d_in[13];
    const float* b2      = (const float*)d_in[14];
    const float* lnf_g   = (const float*)d_in[15];
    const float* lnf_b   = (const float*)d_in[16];
    const float* lm_w    = (const float*)d_in[17];
    const float* lm_b    = (const float*)d_in[18];
    const int*   idx     = (const int*)d_in[19];
    const int*   targets = (const int*)d_in[20];

    float *x, *lg, *tl;
    double* part;
    cudaGetSymbolAddress((void**)&x,  g_x);
    cudaGetSymbolAddress((void**)&lg, g_logits);
    cudaGetSymbolAddress((void**)&tl, g_tokloss);
    cudaGetSymbolAddress((void**)&part, g_partial);

    float* outp = (float*)d_out;
    const long LSZ = (long)NTOK * NVOCAB;
    float* logits = ((long)out_size >= LSZ) ? outp : lg;
    float* lossp;
    if ((long)out_size >= LSZ + 1)      lossp = outp + LSZ;
    else if (out_size == 1)             lossp = outp;
    else                                lossp = tl;

    const int ATTN_SMEM = 54784 * 2;                          // 109568 B
    const int FFN_SMEM  = (44544 + 9216) * 2;                 // 107520 B
    const int FFN2_SMEM = (44544 + 5184) * 2 + 128 * 66 * 4;  // 133248 B
    cudaFuncSetAttribute(attn_p<0>, cudaFuncAttributeMaxDynamicSharedMemorySize, ATTN_SMEM);
    cudaFuncSetAttribute(attn_p<1>, cudaFuncAttributeMaxDynamicSharedMemorySize, ATTN_SMEM);
    cudaFuncSetAttribute(ffn_p<0>,  cudaFuncAttributeMaxDynamicSharedMemorySize, FFN_SMEM);
    cudaFuncSetAttribute(ffn_p<2>,  cudaFuncAttributeMaxDynamicSharedMemorySize, FFN2_SMEM);

    for (int l = 0; l < NLAYER; l++) {
        if (l == 0) {
            attn_p<1><<<PGRID, 1024, ATTN_SMEM>>>(
                x, idx, tok_emb, pos_emb, ln1_g, ln1_b,
                wq, wk, wv, wo, bo);
        } else {
            attn_p<0><<<PGRID, 1024, ATTN_SMEM>>>(
                x, idx, tok_emb, pos_emb,
                ln1_g + l * 64, ln1_b + l * 64,
                wq + (long)l * 4096, wk + (long)l * 4096, wv + (long)l * 4096,
                wo + (long)l * 4096, bo + l * 64);
        }
        if (l < NLAYER - 1) {
            ffn_p<0><<<PGRID, 1024, FFN_SMEM>>>(
                x, ln2_g + l * 64, ln2_b + l * 64,
                w1 + (long)l * 64 * 256, b1 + l * 256,
                w2 + (long)l * 256 * 64, b2 + l * 64,
                lnf_g, lnf_b, lm_w, lm_b, targets, logits, tl);
        } else {
            ffn_p<2><<<PGRID, 1024, FFN2_SMEM>>>(
                x, ln2_g + l * 64, ln2_b + l * 64,
                w1 + (long)l * 64 * 256, b1 + l * 256,
                w2 + (long)l * 256 * 64, b2 + l * 64,
                lnf_g, lnf_b, lm_w, lm_b, targets, logits, tl);
        }
    }
    reduce1_kernel<<<512, 256>>>(tl, part);
    reduce2_kernel<<<1, 512>>>(part, lossp);
}